// round 6
// baseline (speedup 1.0000x reference)
#include <cuda_runtime.h>
#include <cuda_bf16.h>
#include <cstdint>
#include <math.h>

#define BB 4
#define TT 2048
#define DD 1024
#define HH 16
#define KK 64
#define BT (BB*TT)          /* 8192 tokens */
#define SCH 32              /* chunk length (numerically safe in fp32) */
#define NCH (TT/SCH)        /* 64 chunks per sequence */
#define NBH (BB*HH)         /* 64 (batch,head) pairs */
#define LOGMIN (-5.2983174f) /* log(0.005) */
#define LN_EPS 6.4e-4f       /* 1e-5 * 8^2 */

// ---------------- scratch (static device arrays; no runtime allocation) ----
static __device__ float g_xx   [BT*DD];
static __device__ float g_xmix [BT*DD];
static __device__ float g_xxx  [BT*160];
static __device__ float g_xw   [BT*DD];
static __device__ float g_xk   [BT*DD];
static __device__ float g_xv   [BT*DD];
static __device__ float g_xr   [BT*DD];
static __device__ float g_xg   [BT*DD];
static __device__ float g_r    [BT*DD];
static __device__ float g_k    [BT*DD];
static __device__ float g_v    [BT*DD];
static __device__ float g_gate [BT*DD];
static __device__ float g_w    [BT*DD];
static __device__ float g_t1   [BT*64];
static __device__ float g_rw   [BT*DD];
static __device__ float g_att  [BT*DD];
static __device__ float g_yn   [BT*DD];
static __device__ float g_wkvc [NBH*NCH*KK*KK];
static __device__ float g_states[NBH*NCH*KK*KK];
static __device__ float g_expws[NBH*NCH*KK];
// pre-rounded (tf32) weight copies
static __device__ float g_Wr  [DD*DD];
static __device__ float g_Wk  [DD*DD];
static __device__ float g_Wv  [DD*DD];
static __device__ float g_Wg  [DD*DD];
static __device__ float g_Wo  [DD*DD];
static __device__ float g_w1r [DD*160];
static __device__ float g_dw1r[DD*64];
static __device__ float g_dw2r[64*DD];

__device__ __forceinline__ float to_tf32f(float x) {
    uint32_t u;
    asm("cvt.rna.tf32.f32 %0, %1;" : "=r"(u) : "f"(x));
    return __uint_as_float(u);
}

// ---------------- kernel 0: round weights to tf32 once ----------------------
struct RoundArgs { const float* src[8]; float* dst[8]; int n[8]; };

__global__ __launch_bounds__(256) void round_weights(RoundArgs a)
{
    int which = blockIdx.y;
    int n = a.n[which];
    int idx = blockIdx.x * 256 + threadIdx.x;
    if (idx < n) a.dst[which][idx] = to_tf32f(a.src[which][idx]);
}

// ---------------- kernel 1: token shift + mix input ------------------------
__global__ void prep_kernel(const float* __restrict__ x, const float* __restrict__ tmx,
                            float* __restrict__ xx, float* __restrict__ xmix)
{
    size_t idx = (size_t)blockIdx.x * 256 + threadIdx.x;
    int d = (int)(idx & (DD - 1));
    int t = (int)((idx >> 10) & (TT - 1));   // DD = 2^10
    float xv = x[idx];
    float prev = (t == 0) ? 0.f : x[idx - DD];
    float xxv = prev - xv;
    xx[idx] = xxv;
    xmix[idx] = to_tf32f(xv + xxv * tmx[d]);
}

// ---------------- tf32 tensor-core GEMM (operands pre-rounded) --------------
__device__ __forceinline__ void cp16(void* smem_dst, const void* gmem_src, bool pred) {
    uint32_t saddr = (uint32_t)__cvta_generic_to_shared(smem_dst);
    if (pred)
        asm volatile("cp.async.cg.shared.global [%0], [%1], 16;\n"
                     :: "r"(saddr), "l"(gmem_src));
    else
        asm volatile("cp.async.cg.shared.global [%0], [%1], 16, 0;\n"
                     :: "r"(saddr), "l"(gmem_src));
}

// epi: 0 none, 1 tanh, 2 silu, 3 -exp(bias[n]+v), 4 tanh+tf32round
__device__ __forceinline__ float apply_epi(float v, int epi, const float* bias, int n) {
    if (epi == 1) return tanhf(v);
    if (epi == 2) return v * (1.f / (1.f + expf(-v)));
    if (epi == 3) return -expf(bias[n] + v);
    if (epi == 4) return to_tf32f(tanhf(v));
    return v;
}

// 128x128 CTA tile, BK=16, 8 warps (2x4), warp tile 64x32, mma.m16n8k8.tf32
__device__ __forceinline__ void gemm_body(
    const float* __restrict__ A, const float* __restrict__ B,
    float* __restrict__ C, int N, int Kd, const float* __restrict__ bias,
    int epi, int m0, int n0,
    float (*As)[128][20], float (*Bs)[16][136])
{
    const int tid  = threadIdx.x;
    const int lane = tid & 31;
    const int wid  = tid >> 5;
    const int wm   = wid >> 2;
    const int wn   = wid & 3;

    float acc[4][4][4];
#pragma unroll
    for (int i = 0; i < 4; i++)
#pragma unroll
        for (int j = 0; j < 4; j++)
#pragma unroll
            for (int r = 0; r < 4; r++) acc[i][j][r] = 0.f;

    const int arow = tid >> 2;
    const int acol = (tid & 3) << 2;
    const int brow = tid >> 5;
    const int bcol = (tid & 31) << 2;
    const bool bpred = (n0 + bcol) < N;

    auto load_chunk = [&](int k0, int buf) {
#pragma unroll
        for (int r = 0; r < 2; r++) {
            int mr = arow + (r << 6);
            cp16(&As[buf][mr][acol], A + (size_t)(m0 + mr) * Kd + k0 + acol, true);
        }
#pragma unroll
        for (int r = 0; r < 2; r++) {
            int kr = brow + (r << 3);
            cp16(&Bs[buf][kr][bcol], B + (size_t)(k0 + kr) * N + n0 + bcol, bpred);
        }
        asm volatile("cp.async.commit_group;\n");
    };

    auto compute = [&](int buf) {
#pragma unroll
        for (int ks = 0; ks < 2; ks++) {
            const int kb   = (ks << 3) + (lane & 3);
            const int mrow = (wm << 6) + (lane >> 2);
            const int ncol = (wn << 5) + (lane >> 2);
            uint32_t af[4][4], bf[4][2];
#pragma unroll
            for (int mi = 0; mi < 4; mi++) {
                af[mi][0] = __float_as_uint(As[buf][mrow + mi*16    ][kb    ]);
                af[mi][1] = __float_as_uint(As[buf][mrow + mi*16 + 8][kb    ]);
                af[mi][2] = __float_as_uint(As[buf][mrow + mi*16    ][kb + 4]);
                af[mi][3] = __float_as_uint(As[buf][mrow + mi*16 + 8][kb + 4]);
            }
#pragma unroll
            for (int ni = 0; ni < 4; ni++) {
                bf[ni][0] = __float_as_uint(Bs[buf][kb    ][ncol + ni*8]);
                bf[ni][1] = __float_as_uint(Bs[buf][kb + 4][ncol + ni*8]);
            }
#pragma unroll
            for (int mi = 0; mi < 4; mi++)
#pragma unroll
                for (int ni = 0; ni < 4; ni++)
                    asm volatile(
                        "mma.sync.aligned.m16n8k8.row.col.f32.tf32.tf32.f32 "
                        "{%0,%1,%2,%3}, {%4,%5,%6,%7}, {%8,%9}, {%0,%1,%2,%3};\n"
                        : "+f"(acc[mi][ni][0]), "+f"(acc[mi][ni][1]),
                          "+f"(acc[mi][ni][2]), "+f"(acc[mi][ni][3])
                        : "r"(af[mi][0]), "r"(af[mi][1]), "r"(af[mi][2]), "r"(af[mi][3]),
                          "r"(bf[ni][0]), "r"(bf[ni][1]));
        }
    };

    load_chunk(0, 0);
    asm volatile("cp.async.wait_group 0;\n");
    __syncthreads();

    const int nK = Kd >> 4;
    for (int kc = 0; kc < nK; kc++) {
        int buf = kc & 1;
        if (kc + 1 < nK) load_chunk((kc + 1) << 4, buf ^ 1);
        else asm volatile("cp.async.commit_group;\n");
        compute(buf);
        asm volatile("cp.async.wait_group 0;\n");
        __syncthreads();
    }

    // epilogue: float2 stores (n, n+1 adjacent)
#pragma unroll
    for (int mi = 0; mi < 4; mi++) {
        int m = m0 + (wm << 6) + mi*16 + (lane >> 2);
#pragma unroll
        for (int ni = 0; ni < 4; ni++) {
            int n = n0 + (wn << 5) + ni*8 + ((lane & 3) << 1);
            if (n < N) {
                float2 v0, v1;
                v0.x = apply_epi(acc[mi][ni][0], epi, bias, n);
                v0.y = apply_epi(acc[mi][ni][1], epi, bias, n + 1);
                v1.x = apply_epi(acc[mi][ni][2], epi, bias, n);
                v1.y = apply_epi(acc[mi][ni][3], epi, bias, n + 1);
                *(float2*)(C + (size_t)m * N + n) = v0;
                *(float2*)(C + (size_t)(m + 8) * N + n) = v1;
            }
        }
    }
}

template<int EPI>
__global__ __launch_bounds__(256) void gemm_tf32(
    const float* __restrict__ A, const float* __restrict__ B,
    float* __restrict__ C, int M, int N, int Kd, const float* __restrict__ bias)
{
    __shared__ float As[2][128][20];
    __shared__ float Bs[2][16][136];
    int n0 = blockIdx.x << 7;
    if (n0 >= N) return;
    gemm_body(A, B, C, N, Kd, bias, EPI, blockIdx.y << 7, n0, As, Bs);
}

// batched variant: z selects one of 5 independent GEMMs (all Kd=1024)
struct BatchArgs {
    const float* A[5];
    const float* B[5];
    float*       C[5];
    int          N[5];
    int          epi[5];
};

__global__ __launch_bounds__(256) void gemm_tf32_batch(BatchArgs args)
{
    __shared__ float As[2][128][20];
    __shared__ float Bs[2][16][136];
    int z = blockIdx.z;
    int N = args.N[z];
    int n0 = blockIdx.x << 7;
    if (n0 >= N) return;
    gemm_body(args.A[z], args.B[z], args.C[z], N, DD, nullptr,
              args.epi[z], blockIdx.y << 7, n0, As, Bs);
}

// ---------------- kernel 3: 5-branch LoRA mix -------------------------------
__global__ __launch_bounds__(256) void branch_mix(
    const float* __restrict__ x, const float* __restrict__ xx,
    const float* __restrict__ xxx, const float* __restrict__ W2,
    const float* __restrict__ tmw, const float* __restrict__ tmk,
    const float* __restrict__ tmv, const float* __restrict__ tmr,
    const float* __restrict__ tmg,
    float* __restrict__ xw, float* __restrict__ xk, float* __restrict__ xv,
    float* __restrict__ xr, float* __restrict__ xg)
{
    __shared__ float sx[16][160];
    int tid = threadIdx.x;
    int t0 = blockIdx.x * 16;
    int d  = blockIdx.y * 256 + tid;
    for (int e = tid; e < 16 * 160; e += 256) {
        int tok = e / 160, c = e - tok * 160;
        sx[tok][c] = xxx[(size_t)(t0 + tok) * 160 + c];
    }
    __syncthreads();
    float m[5][16];
#pragma unroll
    for (int f = 0; f < 5; f++)
#pragma unroll
        for (int tok = 0; tok < 16; tok++) m[f][tok] = 0.f;
    for (int f = 0; f < 5; f++) {
        for (int i = 0; i < 32; i++) {
            float wv = W2[(size_t)(f * 32 + i) * DD + d];
#pragma unroll
            for (int tok = 0; tok < 16; tok++) m[f][tok] += sx[tok][f * 32 + i] * wv;
        }
    }
    float t_w = tmw[d], t_k = tmk[d], t_v = tmv[d], t_r = tmr[d], t_g = tmg[d];
    for (int tok = 0; tok < 16; tok++) {
        size_t gi = (size_t)(t0 + tok) * DD + d;
        float xv_ = x[gi], xxv = xx[gi];
        xw[gi] = to_tf32f(xv_ + xxv * (t_w + m[0][tok]));
        xk[gi] = to_tf32f(xv_ + xxv * (t_k + m[1][tok]));
        xv[gi] = to_tf32f(xv_ + xxv * (t_v + m[2][tok]));
        xr[gi] = to_tf32f(xv_ + xxv * (t_r + m[3][tok]));
        xg[gi] = to_tf32f(xv_ + xxv * (t_g + m[4][tok]));
    }
}

// ---------------- WKV pass 1: per-chunk intra work + summaries --------------
#define PAD 4
__global__ __launch_bounds__(256) void wkv_chunk(
    const float* __restrict__ r, const float* __restrict__ k,
    const float* __restrict__ v, const float* __restrict__ w,
    const float* __restrict__ u,
    float* __restrict__ rw, float* __restrict__ att,
    float* __restrict__ wkvc, float* __restrict__ expws)
{
    __shared__ float sr [SCH][KK + PAD];
    __shared__ float sk [SCH][KK + PAD];
    __shared__ float sv [SCH][KK + PAD];
    __shared__ float swl[SCH][KK + PAD];   // wlog -> kw
    __shared__ float swc[SCH][KK + PAD];   // cumsum; later reused for A
    __shared__ float soff[KK];
    __shared__ float sdiag[SCH];
    float* sA = &swc[0][0];                // 1024 floats inside swc region

    int tid = threadIdx.x;
    int bid = blockIdx.x;
    int n = bid & (NCH - 1);
    int h = (bid / NCH) & (HH - 1);
    int b = bid / (NCH * HH);
    size_t base = ((size_t)(b * TT + n * SCH)) * DD + h * KK;

    for (int e = tid; e < SCH * KK; e += 256) {
        int t = e >> 6, c = e & 63;
        size_t gi = base + (size_t)t * DD + c;
        sr [t][c] = r[gi];
        sk [t][c] = k[gi];
        sv [t][c] = v[gi];
        swl[t][c] = fmaxf(w[gi], LOGMIN);
    }
    __syncthreads();
    if (tid < KK) {
        float c = 0.f;
        for (int t = 0; t < SCH; t++) { c += swl[t][tid]; swc[t][tid] = c; }
        expws[(size_t)bid * KK + tid] = expf(c);
        soff[tid] = swc[16][tid] - swl[16][tid];
    }
    __syncthreads();
    if (tid < SCH) {   // diagonal: sum_k r*u*k
        float acc = 0.f;
        const float4* rp = (const float4*)&sr[tid][0];
        const float4* kp = (const float4*)&sk[tid][0];
        const float4* up = (const float4*)(u + h * KK);
        for (int c = 0; c < 16; c++) {
            float4 a = rp[c], bb = kp[c], uu = up[c];
            acc += a.x*uu.x*bb.x + a.y*uu.y*bb.y + a.z*uu.z*bb.z + a.w*uu.w*bb.w;
        }
        sdiag[tid] = acc;
    }
    __syncthreads();
    // elementwise transforms (overwrite sr->r_decay, sk->k_inv, swl->kw)
    for (int e = tid; e < SCH * KK; e += 256) {
        int t = e >> 6, c = e & 63;
        float wl = swl[t][c], wc = swc[t][c];
        float shft = wc - wl;
        float off  = soff[c];
        float ws   = swc[SCH - 1][c];
        float rv = sr[t][c], kv = sk[t][c];
        rw[base + (size_t)t * DD + c] = rv * expf(shft);       // r * w_intra
        sr [t][c] = rv * expf(shft - off);                     // r_decay
        sk [t][c] = kv * expf(off - wc);                       // k_inv
        swl[t][c] = kv * expf(ws - wc);                        // k * w_inter
    }
    __syncthreads();
    // A = tril(r_decay @ k_inv^T, -1) + diag  (32x32) -> swc region
    for (int e = tid; e < SCH * SCH; e += 256) {
        int i = e >> 5, j = e & 31;
        float acc = 0.f;
        if (i > j) {
            const float4* rp = (const float4*)&sr[i][0];
            const float4* kp = (const float4*)&sk[j][0];
#pragma unroll 4
            for (int c = 0; c < 16; c++) {
                float4 a = rp[c], bb = kp[c];
                acc += a.x*bb.x + a.y*bb.y + a.z*bb.z + a.w*bb.w;
            }
        } else if (i == j) acc = sdiag[i];
        sA[e] = acc;
    }
    __syncthreads();
    // intra-chunk output: out = A @ v   (thread = (t, 4 v-cols))
    for (int item = tid; item < SCH * 16; item += 256) {
        int t = item >> 4, v4 = item & 15;
        float4 acc = {0.f, 0.f, 0.f, 0.f};
        const float* arow = sA + t * SCH;
        for (int j = 0; j <= t; j++) {
            float a = arow[j];
            float4 vv = *(const float4*)&sv[j][v4 << 2];
            acc.x += a * vv.x; acc.y += a * vv.y;
            acc.z += a * vv.z; acc.w += a * vv.w;
        }
        *(float4*)(att + base + (size_t)t * DD + (v4 << 2)) = acc;
    }
    // chunk summary: wkv_c[c][v] = sum_t kw[t][c]*v[t][v]; thread owns 4x4 tile
    {
        int c0 = (tid >> 4) << 2;
        int v0 = (tid & 15) << 2;
        float acc[4][4];
#pragma unroll
        for (int i = 0; i < 4; i++)
#pragma unroll
            for (int j = 0; j < 4; j++) acc[i][j] = 0.f;
        for (int t = 0; t < SCH; t++) {
            float4 kw = *(const float4*)&swl[t][c0];
            float4 vv = *(const float4*)&sv[t][v0];
            float ka[4] = {kw.x, kw.y, kw.z, kw.w};
            float va[4] = {vv.x, vv.y, vv.z, vv.w};
#pragma unroll
            for (int i = 0; i < 4; i++)
#pragma unroll
                for (int j = 0; j < 4; j++) acc[i][j] += ka[i] * va[j];
        }
        size_t ob = (size_t)bid * (KK * KK);
#pragma unroll
        for (int i = 0; i < 4; i++) {
            float4 o4; o4.x = acc[i][0]; o4.y = acc[i][1];
            o4.z = acc[i][2]; o4.w = acc[i][3];
            *(float4*)(wkvc + ob + (size_t)(c0 + i) * KK + v0) = o4;
        }
    }
}

// ---------------- WKV pass 2: serial scan over chunks -----------------------
__global__ __launch_bounds__(1024) void wkv_scan(
    const float* __restrict__ wkvc, const float* __restrict__ expws,
    float* __restrict__ states)
{
    int bh = blockIdx.x;
    int tid = threadIdx.x;
    int c  = tid >> 4;
    int v0 = (tid & 15) << 2;
    float s0 = 0.f, s1 = 0.f, s2 = 0.f, s3 = 0.f;
    size_t eb = (size_t)bh * NCH * KK;
    size_t sb = (size_t)bh * NCH * KK * KK + (size_t)c * KK + v0;
    for (int n = 0; n < NCH; n++) {
        float wd = expws[eb + (size_t)n * KK + c];
        size_t o = sb + (size_t)n * KK * KK;
        float4 st; st.x = s0; st.y = s1; st.z = s2; st.w = s3;
        *(float4*)(states + o) = st;
        float4 wc4 = *(const float4*)(wkvc + o);
        s0 = s0 * wd + wc4.x; s1 = s1 * wd + wc4.y;
        s2 = s2 * wd + wc4.z; s3 = s3 * wd + wc4.w;
    }
}

// ---------------- WKV pass 3: apply carried state ---------------------------
__global__ __launch_bounds__(256) void wkv_state_out(
    const float* __restrict__ rw, const float* __restrict__ states,
    float* __restrict__ att)
{
    __shared__ float sst[KK][KK];
    __shared__ float srw[SCH][KK];
    int tid = threadIdx.x, bid = blockIdx.x;
    int n = bid & (NCH - 1);
    int h = (bid / NCH) & (HH - 1);
    int b = bid / (NCH * HH);
    size_t base = ((size_t)(b * TT + n * SCH)) * DD + h * KK;
    size_t stb = (size_t)bid * (KK * KK);
    for (int e = tid; e < KK * KK / 4; e += 256)
        ((float4*)&sst[0][0])[e] = ((const float4*)(states + stb))[e];
    for (int e = tid; e < SCH * KK / 4; e += 256) {
        int t = e >> 4, c4 = e & 15;
        ((float4*)&srw[t][0])[c4] =
            *(const float4*)(rw + base + (size_t)t * DD + (c4 << 2));
    }
    __syncthreads();
    // thread owns 2 rows x 4 cols
    int t0 = (tid >> 4) << 1;
    int v0 = (tid & 15) << 2;
    float4 acc0 = {0.f,0.f,0.f,0.f}, acc1 = {0.f,0.f,0.f,0.f};
#pragma unroll 4
    for (int c = 0; c < KK; c++) {
        float4 sv4 = *(const float4*)&sst[c][v0];
        float r0 = srw[t0][c], r1 = srw[t0 + 1][c];
        acc0.x += r0 * sv4.x; acc0.y += r0 * sv4.y;
        acc0.z += r0 * sv4.z; acc0.w += r0 * sv4.w;
        acc1.x += r1 * sv4.x; acc1.y += r1 * sv4.y;
        acc1.z += r1 * sv4.z; acc1.w += r1 * sv4.w;
    }
    float4* o0 = (float4*)(att + base + (size_t)t0 * DD + v0);
    float4* o1 = (float4*)(att + base + (size_t)(t0 + 1) * DD + v0);
    float4 p0 = *o0, p1 = *o1;
    p0.x += acc0.x; p0.y += acc0.y; p0.z += acc0.z; p0.w += acc0.w;
    p1.x += acc1.x; p1.y += acc1.y; p1.z += acc1.z; p1.w += acc1.w;
    *o0 = p0; *o1 = p1;
}

// ---------------- group-norm (per head) + gate ------------------------------
__global__ __launch_bounds__(256) void gnorm_gate(
    const float* __restrict__ att, const float* __restrict__ gate,
    const float* __restrict__ lnw, const float* __restrict__ lnb,
    float* __restrict__ y)
{
    int token = blockIdx.x, tid = threadIdx.x;
    size_t base = (size_t)token * DD + tid * 4;
    float4 v4 = *(const float4*)(att + base);
    float s  = v4.x + v4.y + v4.z + v4.w;
    float ss = v4.x * v4.x + v4.y * v4.y + v4.z * v4.z + v4.w * v4.w;
#pragma unroll
    for (int o = 1; o < 16; o <<= 1) {
        s  += __shfl_xor_sync(0xffffffffu, s,  o);
        ss += __shfl_xor_sync(0xffffffffu, ss, o);
    }
    float mean = s * (1.f / KK);
    float var  = ss * (1.f / KK) - mean * mean;
    float rstd = rsqrtf(var + LN_EPS);
    float4 g4 = *(const float4*)(gate + base);
    float4 w4 = *(const float4*)(lnw + tid * 4);
    float4 b4 = *(const float4*)(lnb + tid * 4);
    float4 o4;
    o4.x = to_tf32f(((v4.x - mean) * rstd * w4.x + b4.x) * g4.x);
    o4.y = to_tf32f(((v4.y - mean) * rstd * w4.y + b4.y) * g4.y);
    o4.z = to_tf32f(((v4.z - mean) * rstd * w4.z + b4.z) * g4.z);
    o4.w = to_tf32f(((v4.w - mean) * rstd * w4.w + b4.w) * g4.w);
    *(float4*)(y + base) = o4;
}

// ---------------- launch ----------------------------------------------------
extern "C" void kernel_launch(void* const* d_in, const int* in_sizes, int n_in,
                              void* d_out, int out_size)
{
    const float* x     = (const float*)d_in[0];
    const float* tmx   = (const float*)d_in[1];
    const float* tmw   = (const float*)d_in[2];
    const float* tmk   = (const float*)d_in[3];
    const float* tmv   = (const float*)d_in[4];
    const float* tmr   = (const float*)d_in[5];
    const float* tmg   = (const float*)d_in[6];
    const float* w1    = (const float*)d_in[7];
    const float* w2    = (const float*)d_in[8];
    const float* tdec  = (const float*)d_in[9];
    const float* dw1   = (const float*)d_in[10];
    const float* dw2   = (const float*)d_in[11];
    const float* faaaa = (const float*)d_in[12];
    const float* Wr    = (const float*)d_in[13];
    const float* Wk    = (const float*)d_in[14];
    const float* Wv    = (const float*)d_in[15];
    const float* Wg    = (const float*)d_in[16];
    const float* Wo    = (const float*)d_in[17];
    const float* lnw   = (const float*)d_in[18];
    const float* lnb   = (const float*)d_in[19];
    float* out = (float*)d_out;

    float *p_xx, *p_xmix, *p_xxx, *p_xw, *p_xk, *p_xv, *p_xr, *p_xg;
    float *p_r, *p_k, *p_v, *p_gate, *p_w, *p_t1, *p_rw, *p_att, *p_yn;
    float *p_wkvc, *p_states, *p_expws;
    float *p_Wr, *p_Wk, *p_Wv, *p_Wg, *p_Wo, *p_w1r, *p_dw1r, *p_dw2r;
    cudaGetSymbolAddress((void**)&p_xx,    g_xx);
    cudaGetSymbolAddress((void**)&p_xmix,  g_xmix);
    cudaGetSymbolAddress((void**)&p_xxx,   g_xxx);
    cudaGetSymbolAddress((void**)&p_xw,    g_xw);
    cudaGetSymbolAddress((void**)&p_xk,    g_xk);
    cudaGetSymbolAddress((void**)&p_xv,    g_xv);
    cudaGetSymbolAddress((void**)&p_xr,    g_xr);
    cudaGetSymbolAddress((void**)&p_xg,    g_xg);
    cudaGetSymbolAddress((void**)&p_r,     g_r);
    cudaGetSymbolAddress((void**)&p_k,     g_k);
    cudaGetSymbolAddress((void**)&p_v,     g_v);
    cudaGetSymbolAddress((void**)&p_gate,  g_gate);
    cudaGetSymbolAddress((void**)&p_w,     g_w);
    cudaGetSymbolAddress((void**)&p_t1,    g_t1);
    cudaGetSymbolAddress((void**)&p_rw,    g_rw);
    cudaGetSymbolAddress((void**)&p_att,   g_att);
    cudaGetSymbolAddress((void**)&p_yn,    g_yn);
    cudaGetSymbolAddress((void**)&p_wkvc,  g_wkvc);
    cudaGetSymbolAddress((void**)&p_states,g_states);
    cudaGetSymbolAddress((void**)&p_expws, g_expws);
    cudaGetSymbolAddress((void**)&p_Wr,    g_Wr);
    cudaGetSymbolAddress((void**)&p_Wk,    g_Wk);
    cudaGetSymbolAddress((void**)&p_Wv,    g_Wv);
    cudaGetSymbolAddress((void**)&p_Wg,    g_Wg);
    cudaGetSymbolAddress((void**)&p_Wo,    g_Wo);
    cudaGetSymbolAddress((void**)&p_w1r,   g_w1r);
    cudaGetSymbolAddress((void**)&p_dw1r,  g_dw1r);
    cudaGetSymbolAddress((void**)&p_dw2r,  g_dw2r);

    // 0. round weights to tf32 (deterministic, runs every call)
    RoundArgs ra;
    ra.src[0] = Wr;  ra.dst[0] = p_Wr;   ra.n[0] = DD * DD;
    ra.src[1] = Wk;  ra.dst[1] = p_Wk;   ra.n[1] = DD * DD;
    ra.src[2] = Wv;  ra.dst[2] = p_Wv;   ra.n[2] = DD * DD;
    ra.src[3] = Wg;  ra.dst[3] = p_Wg;   ra.n[3] = DD * DD;
    ra.src[4] = Wo;  ra.dst[4] = p_Wo;   ra.n[4] = DD * DD;
    ra.src[5] = w1;  ra.dst[5] = p_w1r;  ra.n[5] = DD * 160;
    ra.src[6] = dw1; ra.dst[6] = p_dw1r; ra.n[6] = DD * 64;
    ra.src[7] = dw2; ra.dst[7] = p_dw2r; ra.n[7] = 64 * DD;
    round_weights<<<dim3((DD * DD + 255) / 256, 8), 256>>>(ra);
    // 1. token shift + mix input (xmix pre-rounded)
    prep_kernel<<<(BT * DD) / 256, 256>>>(x, tmx, p_xx, p_xmix);
    // 2. xxx = tanh(xmix @ W1)
    gemm_tf32<1><<<dim3(2, 64), 256>>>(p_xmix, p_w1r, p_xxx, BT, 160, DD, nullptr);
    // 3. five branch inputs (pre-rounded)
    branch_mix<<<dim3(BT / 16, 4), 256>>>(x, p_xx, p_xxx, w2,
                                          tmw, tmk, tmv, tmr, tmg,
                                          p_xw, p_xk, p_xv, p_xr, p_xg);
    // 4. batched: r/k/v projections, gate (silu), decay LoRA stage 1 (tanh+round)
    BatchArgs ba;
    ba.A[0] = p_xr; ba.B[0] = p_Wr;   ba.C[0] = p_r;    ba.N[0] = DD; ba.epi[0] = 0;
    ba.A[1] = p_xk; ba.B[1] = p_Wk;   ba.C[1] = p_k;    ba.N[1] = DD; ba.epi[1] = 0;
    ba.A[2] = p_xv; ba.B[2] = p_Wv;   ba.C[2] = p_v;    ba.N[2] = DD; ba.epi[2] = 0;
    ba.A[3] = p_xg; ba.B[3] = p_Wg;   ba.C[3] = p_gate; ba.N[3] = DD; ba.epi[3] = 2;
    ba.A[4] = p_xw; ba.B[4] = p_dw1r; ba.C[4] = p_t1;   ba.N[4] = 64; ba.epi[4] = 4;
    gemm_tf32_batch<<<dim3(8, 64, 5), 256>>>(ba);
    // 5. w = -exp(time_decay + t1 @ dw2)
    gemm_tf32<3><<<dim3(8, 64), 256>>>(p_t1, p_dw2r, p_w, BT, DD, 64, tdec);
    // 6. WKV
    wkv_chunk<<<NBH * NCH, 256>>>(p_r, p_k, p_v, p_w, faaaa,
                                  p_rw, p_att, p_wkvc, p_expws);
    wkv_scan<<<NBH, 1024>>>(p_wkvc, p_expws, p_states);
    wkv_state_out<<<NBH * NCH, 256>>>(p_rw, p_states, p_att);
    // 7. group-norm + gate (yn pre-rounded), then output projection
    gnorm_gate<<<BT, 256>>>(p_att, p_gate, lnw, lnb, p_yn);
    gemm_tf32<0><<<dim3(8, 64), 256>>>(p_yn, p_Wo, out, BT, DD, DD, nullptr);
}

// round 10
// speedup vs baseline: 1.0880x; 1.0880x over previous
#include <cuda_runtime.h>
#include <cuda_bf16.h>
#include <cstdint>
#include <math.h>

#define BB 4
#define TT 2048
#define DD 1024
#define HH 16
#define KK 64
#define BT (BB*TT)          /* 8192 tokens */
#define SCH 32              /* chunk length (numerically safe in fp32) */
#define NCH (TT/SCH)        /* 64 chunks per sequence */
#define NBH (BB*HH)         /* 64 (batch,head) pairs */
#define LOGMIN (-5.2983174f) /* log(0.005) */
#define LN_EPS 6.4e-4f       /* 1e-5 * 8^2 */

// ---------------- scratch (static device arrays; no runtime allocation) ----
static __device__ float g_xmix [BT*DD];
static __device__ float g_xxx  [BT*160];
static __device__ float g_xw   [BT*DD];
static __device__ float g_xk   [BT*DD];
static __device__ float g_xv   [BT*DD];
static __device__ float g_xr   [BT*DD];
static __device__ float g_xg   [BT*DD];
static __device__ float g_r    [BT*DD];
static __device__ float g_k    [BT*DD];
static __device__ float g_v    [BT*DD];
static __device__ float g_gate [BT*DD];
static __device__ float g_w    [BT*DD];
static __device__ float g_t1   [BT*64];
static __device__ float g_rw   [BT*DD];
static __device__ float g_att  [BT*DD];
static __device__ float g_yn   [BT*DD];
static __device__ float g_wkvc [NBH*NCH*KK*KK];
static __device__ float g_states[NBH*NCH*KK*KK];
static __device__ float g_expws[NBH*NCH*KK];

__device__ __forceinline__ float to_tf32f(float x) {
    uint32_t u;
    asm("cvt.rna.tf32.f32 %0, %1;" : "=r"(u) : "f"(x));
    return __uint_as_float(u);
}

__device__ __forceinline__ uint32_t cvt_tf32(float x) {
    uint32_t r;
    asm("cvt.rna.tf32.f32 %0, %1;" : "=r"(r) : "f"(x));
    return r;
}

// ---------------- kernel 1: token shift + mix input ------------------------
__global__ void prep_kernel(const float* __restrict__ x, const float* __restrict__ tmx,
                            float* __restrict__ xmix)
{
    size_t idx = (size_t)blockIdx.x * 256 + threadIdx.x;
    int d = (int)(idx & (DD - 1));
    int t = (int)((idx >> 10) & (TT - 1));   // DD = 2^10
    float xv = x[idx];
    float prev = (t == 0) ? 0.f : x[idx - DD];
    float xxv = prev - xv;
    xmix[idx] = xv + xxv * tmx[d];
}

// ---------------- tf32 tensor-core GEMM ------------------------------------
__device__ __forceinline__ void cp16(void* smem_dst, const void* gmem_src, bool pred) {
    uint32_t saddr = (uint32_t)__cvta_generic_to_shared(smem_dst);
    if (pred)
        asm volatile("cp.async.cg.shared.global [%0], [%1], 16;\n"
                     :: "r"(saddr), "l"(gmem_src));
    else
        asm volatile("cp.async.cg.shared.global [%0], [%1], 16, 0;\n"
                     :: "r"(saddr), "l"(gmem_src));
}

// epi: 0 none, 1 tanh, 2 silu, 3 -exp(bias[n]+v)
__device__ __forceinline__ float apply_epi(float v, int epi, const float* bias, int n) {
    if (epi == 1) return tanhf(v);
    if (epi == 2) return v * (1.f / (1.f + expf(-v)));
    if (epi == 3) return -expf(bias[n] + v);
    return v;
}

// 128x128 CTA tile, BK=16, 8 warps (2x4), warp tile 64x32, mma.m16n8k8.tf32
__device__ __forceinline__ void gemm_body(
    const float* __restrict__ A, const float* __restrict__ B,
    float* __restrict__ C, int N, int Kd, const float* __restrict__ bias,
    int epi, int m0, int n0,
    float (*As)[128][20], float (*Bs)[16][136])
{
    const int tid  = threadIdx.x;
    const int lane = tid & 31;
    const int wid  = tid >> 5;
    const int wm   = wid >> 2;
    const int wn   = wid & 3;

    float acc[4][4][4];
#pragma unroll
    for (int i = 0; i < 4; i++)
#pragma unroll
        for (int j = 0; j < 4; j++)
#pragma unroll
            for (int r = 0; r < 4; r++) acc[i][j][r] = 0.f;

    const int arow = tid >> 2;
    const int acol = (tid & 3) << 2;
    const int brow = tid >> 5;
    const int bcol = (tid & 31) << 2;
    const bool bpred = (n0 + bcol) < N;

    auto load_chunk = [&](int k0, int buf) {
#pragma unroll
        for (int r = 0; r < 2; r++) {
            int mr = arow + (r << 6);
            cp16(&As[buf][mr][acol], A + (size_t)(m0 + mr) * Kd + k0 + acol, true);
        }
#pragma unroll
        for (int r = 0; r < 2; r++) {
            int kr = brow + (r << 3);
            cp16(&Bs[buf][kr][bcol], B + (size_t)(k0 + kr) * N + n0 + bcol, bpred);
        }
        asm volatile("cp.async.commit_group;\n");
    };

    auto compute = [&](int buf) {
#pragma unroll
        for (int ks = 0; ks < 2; ks++) {
            const int kb   = (ks << 3) + (lane & 3);
            const int mrow = (wm << 6) + (lane >> 2);
            const int ncol = (wn << 5) + (lane >> 2);
            uint32_t af[4][4], bf[4][2];
#pragma unroll
            for (int mi = 0; mi < 4; mi++) {
                af[mi][0] = cvt_tf32(As[buf][mrow + mi*16    ][kb    ]);
                af[mi][1] = cvt_tf32(As[buf][mrow + mi*16 + 8][kb    ]);
                af[mi][2] = cvt_tf32(As[buf][mrow + mi*16    ][kb + 4]);
                af[mi][3] = cvt_tf32(As[buf][mrow + mi*16 + 8][kb + 4]);
            }
#pragma unroll
            for (int ni = 0; ni < 4; ni++) {
                bf[ni][0] = cvt_tf32(Bs[buf][kb    ][ncol + ni*8]);
                bf[ni][1] = cvt_tf32(Bs[buf][kb + 4][ncol + ni*8]);
            }
#pragma unroll
            for (int mi = 0; mi < 4; mi++)
#pragma unroll
                for (int ni = 0; ni < 4; ni++)
                    asm volatile(
                        "mma.sync.aligned.m16n8k8.row.col.f32.tf32.tf32.f32 "
                        "{%0,%1,%2,%3}, {%4,%5,%6,%7}, {%8,%9}, {%0,%1,%2,%3};\n"
                        : "+f"(acc[mi][ni][0]), "+f"(acc[mi][ni][1]),
                          "+f"(acc[mi][ni][2]), "+f"(acc[mi][ni][3])
                        : "r"(af[mi][0]), "r"(af[mi][1]), "r"(af[mi][2]), "r"(af[mi][3]),
                          "r"(bf[ni][0]), "r"(bf[ni][1]));
        }
    };

    load_chunk(0, 0);
    asm volatile("cp.async.wait_group 0;\n");
    __syncthreads();

    const int nK = Kd >> 4;
    for (int kc = 0; kc < nK; kc++) {
        int buf = kc & 1;
        if (kc + 1 < nK) load_chunk((kc + 1) << 4, buf ^ 1);
        else asm volatile("cp.async.commit_group;\n");
        compute(buf);
        asm volatile("cp.async.wait_group 0;\n");
        __syncthreads();
    }

    // epilogue: float2 stores (n, n+1 adjacent)
#pragma unroll
    for (int mi = 0; mi < 4; mi++) {
        int m = m0 + (wm << 6) + mi*16 + (lane >> 2);
#pragma unroll
        for (int ni = 0; ni < 4; ni++) {
            int n = n0 + (wn << 5) + ni*8 + ((lane & 3) << 1);
            if (n < N) {
                float2 v0, v1;
                v0.x = apply_epi(acc[mi][ni][0], epi, bias, n);
                v0.y = apply_epi(acc[mi][ni][1], epi, bias, n + 1);
                v1.x = apply_epi(acc[mi][ni][2], epi, bias, n);
                v1.y = apply_epi(acc[mi][ni][3], epi, bias, n + 1);
                *(float2*)(C + (size_t)m * N + n) = v0;
                *(float2*)(C + (size_t)(m + 8) * N + n) = v1;
            }
        }
    }
}

template<int EPI>
__global__ __launch_bounds__(256) void gemm_tf32(
    const float* __restrict__ A, const float* __restrict__ B,
    float* __restrict__ C, int M, int N, int Kd, const float* __restrict__ bias)
{
    __shared__ float As[2][128][20];
    __shared__ float Bs[2][16][136];
    int n0 = blockIdx.x << 7;
    if (n0 >= N) return;
    gemm_body(A, B, C, N, Kd, bias, EPI, blockIdx.y << 7, n0, As, Bs);
}

// batched variant: z selects one of 5 independent GEMMs (all Kd=1024)
struct BatchArgs {
    const float* A[5];
    const float* B[5];
    float*       C[5];
    int          N[5];
    int          epi[5];
};

__global__ __launch_bounds__(256) void gemm_tf32_batch(BatchArgs args)
{
    __shared__ float As[2][128][20];
    __shared__ float Bs[2][16][136];
    int z = blockIdx.z;
    int N = args.N[z];
    int n0 = blockIdx.x << 7;
    if (n0 >= N) return;
    gemm_body(args.A[z], args.B[z], args.C[z], N, DD, nullptr,
              args.epi[z], blockIdx.y << 7, n0, As, Bs);
}

// ---------------- kernel 3: 5-branch LoRA mix (vectorized) ------------------
// block: 320 threads = 5 f-branches x 64 d.  Tile: 16 tokens x 64 d.
// thread owns one (f, d) pair, accumulates m[16] over its 32 LoRA cols.
__global__ __launch_bounds__(320) void branch_mix(
    const float* __restrict__ x,
    const float* __restrict__ xxx, const float* __restrict__ W2,
    const float* __restrict__ tmw, const float* __restrict__ tmk,
    const float* __restrict__ tmv, const float* __restrict__ tmr,
    const float* __restrict__ tmg,
    float* __restrict__ xw, float* __restrict__ xk, float* __restrict__ xv,
    float* __restrict__ xr, float* __restrict__ xg)
{
    __shared__ float sxxxT[160][20];  // [lora_col][token], padded for float4
    __shared__ float sx [16][64];
    __shared__ float sxx[16][64];

    const int tid = threadIdx.x;
    const int t0  = blockIdx.x * 16;      // token tile
    const int d0  = blockIdx.y * 64;      // d tile

    // cooperative loads
    for (int e = tid; e < 16 * 160; e += 320) {
        int tok = e / 160, c = e - tok * 160;
        sxxxT[c][tok] = xxx[(size_t)(t0 + tok) * 160 + c];
    }
    for (int e = tid; e < 16 * 64; e += 320) {
        int t = e >> 6, c = e & 63;
        size_t gi = (size_t)(t0 + t) * DD + d0 + c;
        float xv_ = x[gi];
        float prev = (((t0 + t) & (TT - 1)) == 0) ? 0.f : x[gi - DD];
        sx [t][c] = xv_;
        sxx[t][c] = prev - xv_;
    }
    __syncthreads();

    const int f  = tid >> 6;        // 0..4
    const int dl = tid & 63;
    const int d  = d0 + dl;

    float4 macc[4];
#pragma unroll
    for (int g = 0; g < 4; g++) macc[g] = make_float4(0.f, 0.f, 0.f, 0.f);

    const float* W2f = W2 + (size_t)(f * 32) * DD + d;
#pragma unroll 8
    for (int i = 0; i < 32; i++) {
        float wv = W2f[(size_t)i * DD];
        const float4* xr4 = (const float4*)&sxxxT[f * 32 + i][0];
#pragma unroll
        for (int g = 0; g < 4; g++) {
            float4 xv4 = xr4[g];
            macc[g].x += xv4.x * wv; macc[g].y += xv4.y * wv;
            macc[g].z += xv4.z * wv; macc[g].w += xv4.w * wv;
        }
    }
    float m[16];
#pragma unroll
    for (int g = 0; g < 4; g++) {
        m[g*4+0] = macc[g].x; m[g*4+1] = macc[g].y;
        m[g*4+2] = macc[g].z; m[g*4+3] = macc[g].w;
    }

    const float* tmsel;
    float* osel;
    switch (f) {
        case 0: tmsel = tmw; osel = xw; break;
        case 1: tmsel = tmk; osel = xk; break;
        case 2: tmsel = tmv; osel = xv; break;
        case 3: tmsel = tmr; osel = xr; break;
        default: tmsel = tmg; osel = xg; break;
    }
    float tmv_ = tmsel[d];
#pragma unroll
    for (int tok = 0; tok < 16; tok++) {
        float val = sx[tok][dl] + sxx[tok][dl] * (tmv_ + m[tok]);
        osel[(size_t)(t0 + tok) * DD + d] = val;
    }
}

// ---------------- WKV pass 1: per-chunk intra work + summaries --------------
#define PAD 4
__global__ __launch_bounds__(256) void wkv_chunk(
    const float* __restrict__ r, const float* __restrict__ k,
    const float* __restrict__ v, const float* __restrict__ w,
    const float* __restrict__ u,
    float* __restrict__ rw, float* __restrict__ att,
    float* __restrict__ wkvc, float* __restrict__ expws)
{
    __shared__ float sr [SCH][KK + PAD];
    __shared__ float sk [SCH][KK + PAD];
    __shared__ float sv [SCH][KK + PAD];
    __shared__ float swl[SCH][KK + PAD];   // wlog -> kw
    __shared__ float swc[SCH][KK + PAD];   // cumsum; later reused for A
    __shared__ float soff[KK];
    __shared__ float sdiag[SCH];
    float* sA = &swc[0][0];                // 1024 floats inside swc region

    int tid = threadIdx.x;
    int bid = blockIdx.x;
    int n = bid & (NCH - 1);
    int h = (bid / NCH) & (HH - 1);
    int b = bid / (NCH * HH);
    size_t base = ((size_t)(b * TT + n * SCH)) * DD + h * KK;

    for (int e = tid; e < SCH * KK; e += 256) {
        int t = e >> 6, c = e & 63;
        size_t gi = base + (size_t)t * DD + c;
        sr [t][c] = r[gi];
        sk [t][c] = k[gi];
        sv [t][c] = v[gi];
        swl[t][c] = fmaxf(w[gi], LOGMIN);
    }
    __syncthreads();
    if (tid < KK) {
        float c = 0.f;
        for (int t = 0; t < SCH; t++) { c += swl[t][tid]; swc[t][tid] = c; }
        expws[(size_t)bid * KK + tid] = expf(c);
        soff[tid] = swc[16][tid] - swl[16][tid];
    }
    __syncthreads();
    if (tid < SCH) {   // diagonal: sum_k r*u*k
        float acc = 0.f;
        const float4* rp = (const float4*)&sr[tid][0];
        const float4* kp = (const float4*)&sk[tid][0];
        const float4* up = (const float4*)(u + h * KK);
        for (int c = 0; c < 16; c++) {
            float4 a = rp[c], bb = kp[c], uu = up[c];
            acc += a.x*uu.x*bb.x + a.y*uu.y*bb.y + a.z*uu.z*bb.z + a.w*uu.w*bb.w;
        }
        sdiag[tid] = acc;
    }
    __syncthreads();
    // elementwise transforms (overwrite sr->r_decay, sk->k_inv, swl->kw)
    for (int e = tid; e < SCH * KK; e += 256) {
        int t = e >> 6, c = e & 63;
        float wl = swl[t][c], wc = swc[t][c];
        float shft = wc - wl;
        float off  = soff[c];
        float ws   = swc[SCH - 1][c];
        float rv = sr[t][c], kv = sk[t][c];
        rw[base + (size_t)t * DD + c] = rv * expf(shft);       // r * w_intra
        sr [t][c] = rv * expf(shft - off);                     // r_decay
        sk [t][c] = kv * expf(off - wc);                       // k_inv
        swl[t][c] = kv * expf(ws - wc);                        // k * w_inter
    }
    __syncthreads();
    // A = tril(r_decay @ k_inv^T, -1) + diag  (32x32) -> swc region
    for (int e = tid; e < SCH * SCH; e += 256) {
        int i = e >> 5, j = e & 31;
        float acc = 0.f;
        if (i > j) {
            const float4* rp = (const float4*)&sr[i][0];
            const float4* kp = (const float4*)&sk[j][0];
#pragma unroll 4
            for (int c = 0; c < 16; c++) {
                float4 a = rp[c], bb = kp[c];
                acc += a.x*bb.x + a.y*bb.y + a.z*bb.z + a.w*bb.w;
            }
        } else if (i == j) acc = sdiag[i];
        sA[e] = acc;
    }
    __syncthreads();
    // intra-chunk output: out = A @ v   (thread = (t, 4 v-cols))
    for (int item = tid; item < SCH * 16; item += 256) {
        int t = item >> 4, v4 = item & 15;
        float4 acc = {0.f, 0.f, 0.f, 0.f};
        const float* arow = sA + t * SCH;
        for (int j = 0; j <= t; j++) {
            float a = arow[j];
            float4 vv = *(const float4*)&sv[j][v4 << 2];
            acc.x += a * vv.x; acc.y += a * vv.y;
            acc.z += a * vv.z; acc.w += a * vv.w;
        }
        *(float4*)(att + base + (size_t)t * DD + (v4 << 2)) = acc;
    }
    // chunk summary: wkv_c[c][v] = sum_t kw[t][c]*v[t][v]; thread owns 4x4 tile
    {
        int c0 = (tid >> 4) << 2;
        int v0 = (tid & 15) << 2;
        float acc[4][4];
#pragma unroll
        for (int i = 0; i < 4; i++)
#pragma unroll
            for (int j = 0; j < 4; j++) acc[i][j] = 0.f;
        for (int t = 0; t < SCH; t++) {
            float4 kw = *(const float4*)&swl[t][c0];
            float4 vv = *(const float4*)&sv[t][v0];
            float ka[4] = {kw.x, kw.y, kw.z, kw.w};
            float va[4] = {vv.x, vv.y, vv.z, vv.w};
#pragma unroll
            for (int i = 0; i < 4; i++)
#pragma unroll
                for (int j = 0; j < 4; j++) acc[i][j] += ka[i] * va[j];
        }
        size_t ob = (size_t)bid * (KK * KK);
#pragma unroll
        for (int i = 0; i < 4; i++) {
            float4 o4; o4.x = acc[i][0]; o4.y = acc[i][1];
            o4.z = acc[i][2]; o4.w = acc[i][3];
            *(float4*)(wkvc + ob + (size_t)(c0 + i) * KK + v0) = o4;
        }
    }
}

// ---------------- WKV pass 2: serial scan over chunks -----------------------
__global__ __launch_bounds__(1024) void wkv_scan(
    const float* __restrict__ wkvc, const float* __restrict__ expws,
    float* __restrict__ states)
{
    int bh = blockIdx.x;
    int tid = threadIdx.x;
    int c  = tid >> 4;
    int v0 = (tid & 15) << 2;
    float s0 = 0.f, s1 = 0.f, s2 = 0.f, s3 = 0.f;
    size_t eb = (size_t)bh * NCH * KK;
    size_t sb = (size_t)bh * NCH * KK * KK + (size_t)c * KK + v0;
    for (int n = 0; n < NCH; n++) {
        float wd = expws[eb + (size_t)n * KK + c];
        size_t o = sb + (size_t)n * KK * KK;
        float4 st; st.x = s0; st.y = s1; st.z = s2; st.w = s3;
        *(float4*)(states + o) = st;
        float4 wc4 = *(const float4*)(wkvc + o);
        s0 = s0 * wd + wc4.x; s1 = s1 * wd + wc4.y;
        s2 = s2 * wd + wc4.z; s3 = s3 * wd + wc4.w;
    }
}

// ---------------- WKV pass 3: apply carried state ---------------------------
__global__ __launch_bounds__(256) void wkv_state_out(
    const float* __restrict__ rw, const float* __restrict__ states,
    float* __restrict__ att)
{
    __shared__ float sst[KK][KK];
    __shared__ float srw[SCH][KK];
    int tid = threadIdx.x, bid = blockIdx.x;
    int n = bid & (NCH - 1);
    int h = (bid / NCH) & (HH - 1);
    int b = bid / (NCH * HH);
    size_t base = ((size_t)(b * TT + n * SCH)) * DD + h * KK;
    size_t stb = (size_t)bid * (KK * KK);
    for (int e = tid; e < KK * KK / 4; e += 256)
        ((float4*)&sst[0][0])[e] = ((const float4*)(states + stb))[e];
    for (int e = tid; e < SCH * KK / 4; e += 256) {
        int t = e >> 4, c4 = e & 15;
        ((float4*)&srw[t][0])[c4] =
            *(const float4*)(rw + base + (size_t)t * DD + (c4 << 2));
    }
    __syncthreads();
    // thread owns 2 rows x 4 cols
    int t0 = (tid >> 4) << 1;
    int v0 = (tid & 15) << 2;
    float4 acc0 = {0.f,0.f,0.f,0.f}, acc1 = {0.f,0.f,0.f,0.f};
#pragma unroll 4
    for (int c = 0; c < KK; c++) {
        float4 sv4 = *(const float4*)&sst[c][v0];
        float r0 = srw[t0][c], r1 = srw[t0 + 1][c];
        acc0.x += r0 * sv4.x; acc0.y += r0 * sv4.y;
        acc0.z += r0 * sv4.z; acc0.w += r0 * sv4.w;
        acc1.x += r1 * sv4.x; acc1.y += r1 * sv4.y;
        acc1.z += r1 * sv4.z; acc1.w += r1 * sv4.w;
    }
    float4* o0 = (float4*)(att + base + (size_t)t0 * DD + v0);
    float4* o1 = (float4*)(att + base + (size_t)(t0 + 1) * DD + v0);
    float4 p0 = *o0, p1 = *o1;
    p0.x += acc0.x; p0.y += acc0.y; p0.z += acc0.z; p0.w += acc0.w;
    p1.x += acc1.x; p1.y += acc1.y; p1.z += acc1.z; p1.w += acc1.w;
    *o0 = p0; *o1 = p1;
}

// ---------------- group-norm (per head) + gate ------------------------------
__global__ __launch_bounds__(256) void gnorm_gate(
    const float* __restrict__ att, const float* __restrict__ gate,
    const float* __restrict__ lnw, const float* __restrict__ lnb,
    float* __restrict__ y)
{
    int token = blockIdx.x, tid = threadIdx.x;
    size_t base = (size_t)token * DD + tid * 4;
    float4 v4 = *(const float4*)(att + base);
    float s  = v4.x + v4.y + v4.z + v4.w;
    float ss = v4.x * v4.x + v4.y * v4.y + v4.z * v4.z + v4.w * v4.w;
#pragma unroll
    for (int o = 1; o < 16; o <<= 1) {
        s  += __shfl_xor_sync(0xffffffffu, s,  o);
        ss += __shfl_xor_sync(0xffffffffu, ss, o);
    }
    float mean = s * (1.f / KK);
    float var  = ss * (1.f / KK) - mean * mean;
    float rstd = rsqrtf(var + LN_EPS);
    float4 g4 = *(const float4*)(gate + base);
    float4 w4 = *(const float4*)(lnw + tid * 4);
    float4 b4 = *(const float4*)(lnb + tid * 4);
    float4 o4;
    o4.x = ((v4.x - mean) * rstd * w4.x + b4.x) * g4.x;
    o4.y = ((v4.y - mean) * rstd * w4.y + b4.y) * g4.y;
    o4.z = ((v4.z - mean) * rstd * w4.z + b4.z) * g4.z;
    o4.w = ((v4.w - mean) * rstd * w4.w + b4.w) * g4.w;
    *(float4*)(y + base) = o4;
}

// ---------------- launch ----------------------------------------------------
extern "C" void kernel_launch(void* const* d_in, const int* in_sizes, int n_in,
                              void* d_out, int out_size)
{
    const float* x     = (const float*)d_in[0];
    const float* tmx   = (const float*)d_in[1];
    const float* tmw   = (const float*)d_in[2];
    const float* tmk   = (const float*)d_in[3];
    const float* tmv   = (const float*)d_in[4];
    const float* tmr   = (const float*)d_in[5];
    const float* tmg   = (const float*)d_in[6];
    const float* w1    = (const float*)d_in[7];
    const float* w2    = (const float*)d_in[8];
    const float* tdec  = (const float*)d_in[9];
    const float* dw1   = (const float*)d_in[10];
    const float* dw2   = (const float*)d_in[11];
    const float* faaaa = (const float*)d_in[12];
    const float* Wr    = (const float*)d_in[13];
    const float* Wk    = (const float*)d_in[14];
    const float* Wv    = (const float*)d_in[15];
    const float* Wg    = (const float*)d_in[16];
    const float* Wo    = (const float*)d_in[17];
    const float* lnw   = (const float*)d_in[18];
    const float* lnb   = (const float*)d_in[19];
    float* out = (float*)d_out;

    float *p_xmix, *p_xxx, *p_xw, *p_xk, *p_xv, *p_xr, *p_xg;
    float *p_r, *p_k, *p_v, *p_gate, *p_w, *p_t1, *p_rw, *p_att, *p_yn;
    float *p_wkvc, *p_states, *p_expws;
    cudaGetSymbolAddress((void**)&p_xmix,  g_xmix);
    cudaGetSymbolAddress((void**)&p_xxx,   g_xxx);
    cudaGetSymbolAddress((void**)&p_xw,    g_xw);
    cudaGetSymbolAddress((void**)&p_xk,    g_xk);
    cudaGetSymbolAddress((void**)&p_xv,    g_xv);
    cudaGetSymbolAddress((void**)&p_xr,    g_xr);
    cudaGetSymbolAddress((void**)&p_xg,    g_xg);
    cudaGetSymbolAddress((void**)&p_r,     g_r);
    cudaGetSymbolAddress((void**)&p_k,     g_k);
    cudaGetSymbolAddress((void**)&p_v,     g_v);
    cudaGetSymbolAddress((void**)&p_gate,  g_gate);
    cudaGetSymbolAddress((void**)&p_w,     g_w);
    cudaGetSymbolAddress((void**)&p_t1,    g_t1);
    cudaGetSymbolAddress((void**)&p_rw,    g_rw);
    cudaGetSymbolAddress((void**)&p_att,   g_att);
    cudaGetSymbolAddress((void**)&p_yn,    g_yn);
    cudaGetSymbolAddress((void**)&p_wkvc,  g_wkvc);
    cudaGetSymbolAddress((void**)&p_states,g_states);
    cudaGetSymbolAddress((void**)&p_expws, g_expws);

    // 1. token shift + mix input
    prep_kernel<<<(BT * DD) / 256, 256>>>(x, tmx, p_xmix);
    // 2. xxx = tanh(xmix @ W1)
    gemm_tf32<1><<<dim3(2, 64), 256>>>(p_xmix, w1, p_xxx, BT, 160, DD, nullptr);
    // 3. five branch inputs (fused token-shift recompute)
    branch_mix<<<dim3(BT / 16, DD / 64), 320>>>(x, p_xxx, w2,
                                                tmw, tmk, tmv, tmr, tmg,
                                                p_xw, p_xk, p_xv, p_xr, p_xg);
    // 4. batched: r/k/v projections, gate (silu), decay LoRA stage 1 (tanh)
    BatchArgs ba;
    ba.A[0] = p_xr; ba.B[0] = Wr;  ba.C[0] = p_r;    ba.N[0] = DD; ba.epi[0] = 0;
    ba.A[1] = p_xk; ba.B[1] = Wk;  ba.C[1] = p_k;    ba.N[1] = DD; ba.epi[1] = 0;
    ba.A[2] = p_xv; ba.B[2] = Wv;  ba.C[2] = p_v;    ba.N[2] = DD; ba.epi[2] = 0;
    ba.A[3] = p_xg; ba.B[3] = Wg;  ba.C[3] = p_gate; ba.N[3] = DD; ba.epi[3] = 2;
    ba.A[4] = p_xw; ba.B[4] = dw1; ba.C[4] = p_t1;   ba.N[4] = 64; ba.epi[4] = 1;
    gemm_tf32_batch<<<dim3(8, 64, 5), 256>>>(ba);
    // 5. w = -exp(time_decay + t1 @ dw2)
    gemm_tf32<3><<<dim3(8, 64), 256>>>(p_t1, dw2, p_w, BT, DD, 64, tdec);
    // 6. WKV
    wkv_chunk<<<NBH * NCH, 256>>>(p_r, p_k, p_v, p_w, faaaa,
                                  p_rw, p_att, p_wkvc, p_expws);
    wkv_scan<<<NBH, 1024>>>(p_wkvc, p_expws, p_states);
    wkv_state_out<<<NBH * NCH, 256>>>(p_rw, p_states, p_att);
    // 7. group-norm + gate, then output projection
    gnorm_gate<<<BT, 256>>>(p_att, p_gate, lnw, lnb, p_yn);
    gemm_tf32<0><<<dim3(8, 64), 256>>>(p_yn, Wo, out, BT, DD, DD, nullptr);
}

// round 14
// speedup vs baseline: 1.3276x; 1.2202x over previous
#include <cuda_runtime.h>
#include <cuda_fp16.h>
#include <cuda_bf16.h>
#include <cstdint>
#include <math.h>

#define BB 4
#define TT 2048
#define DD 1024
#define HH 16
#define KK 64
#define BT (BB*TT)          /* 8192 tokens */
#define SCH 32              /* chunk length (numerically safe in fp32) */
#define NCH (TT/SCH)        /* 64 chunks per sequence */
#define NBH (BB*HH)         /* 64 (batch,head) pairs */
#define LOGMIN (-5.2983174f) /* log(0.005) */
#define LN_EPS 6.4e-4f       /* 1e-5 * 8^2 */

// ---------------- scratch (static device arrays; no runtime allocation) ----
static __device__ float g_xmix [BT*DD];
static __device__ float g_xxx  [BT*160];
static __device__ float g_xw   [BT*DD];
static __device__ float g_r    [BT*DD];
static __device__ float g_k    [BT*DD];
static __device__ float g_v    [BT*DD];
static __device__ float g_gate [BT*DD];
static __device__ float g_w    [BT*DD];
static __device__ float g_t1   [BT*64];
static __device__ float g_rw   [BT*DD];
static __device__ float g_att  [BT*DD];
static __device__ float g_wkvc [NBH*NCH*KK*KK];
static __device__ float g_states[NBH*NCH*KK*KK];
static __device__ float g_expws[NBH*NCH*KK];
// fp16 operands for tensor-core GEMMs
static __device__ __half g_xrh [BT*DD];
static __device__ __half g_xkh [BT*DD];
static __device__ __half g_xvh [BT*DD];
static __device__ __half g_xgh [BT*DD];
static __device__ __half g_ynh [BT*DD];
static __device__ __half g_WrH [DD*DD];   // transposed [N,K]
static __device__ __half g_WkH [DD*DD];
static __device__ __half g_WvH [DD*DD];
static __device__ __half g_WgH [DD*DD];
static __device__ __half g_WoH [DD*DD];

__device__ __forceinline__ uint32_t cvt_tf32(float x) {
    uint32_t r;
    asm("cvt.rna.tf32.f32 %0, %1;" : "=r"(r) : "f"(x));
    return r;
}

// ---------------- kernel 0: transpose + fp16-round the 5 big weights -------
struct RepHArgs { const float* src[5]; __half* dst[5]; };

__global__ __launch_bounds__(256) void repack_wh(RepHArgs a)
{
    __shared__ float tile[32][33];
    int z = blockIdx.z;
    const float* W = a.src[z];
    __half* WT = a.dst[z];
    int c0 = blockIdx.x * 32, r0 = blockIdx.y * 32;
    int tx = threadIdx.x & 31, ty = threadIdx.x >> 5;
#pragma unroll
    for (int i = 0; i < 32; i += 8)
        tile[ty + i][tx] = W[(size_t)(r0 + ty + i) * DD + c0 + tx];
    __syncthreads();
#pragma unroll
    for (int i = 0; i < 32; i += 8)
        WT[(size_t)(c0 + ty + i) * DD + r0 + tx] = __float2half_rn(tile[tx][ty + i]);
}

// ---------------- kernel 1: token shift + mix input ------------------------
__global__ void prep_kernel(const float* __restrict__ x, const float* __restrict__ tmx,
                            float* __restrict__ xmix)
{
    size_t idx = (size_t)blockIdx.x * 256 + threadIdx.x;
    int d = (int)(idx & (DD - 1));
    int t = (int)((idx >> 10) & (TT - 1));   // DD = 2^10
    float xv = x[idx];
    float prev = (t == 0) ? 0.f : x[idx - DD];
    float xxv = prev - xv;
    xmix[idx] = xv + xxv * tmx[d];
}

// ---------------- cp.async helper -------------------------------------------
__device__ __forceinline__ void cp16(void* smem_dst, const void* gmem_src, bool pred) {
    uint32_t saddr = (uint32_t)__cvta_generic_to_shared(smem_dst);
    if (pred)
        asm volatile("cp.async.cg.shared.global [%0], [%1], 16;\n"
                     :: "r"(saddr), "l"(gmem_src));
    else
        asm volatile("cp.async.cg.shared.global [%0], [%1], 16, 0;\n"
                     :: "r"(saddr), "l"(gmem_src));
}

// epi: 0 none, 1 tanh, 2 silu, 3 -exp(bias[n]+v)
__device__ __forceinline__ float apply_epi(float v, int epi, const float* bias, int n) {
    if (epi == 1) return tanhf(v);
    if (epi == 2) return v * (1.f / (1.f + expf(-v)));
    if (epi == 3) return -expf(bias[n] + v);
    return v;
}

// ================= fp16 tensor-core GEMM ====================================
// C[M,1024] = A[M,1024]fp16 @ Wt[1024,1024]fp16^T.  A row-major [M,K],
// Wt K-major [N,K].  128x128 CTA tile, BK=32, 8 warps (2x4), warp 64x32,
// mma.m16n8k16.f16 with fp32 accum.  Smem stride 40 halves (80B): lanes'
// row-groups hit banks r*20 mod 32 = {0,20,8,28,16,4,24,12} -> conflict-free.
__device__ __forceinline__ void hgemm_body(
    const __half* __restrict__ A, const __half* __restrict__ Bt,
    float* __restrict__ C, int epi, int m0, int n0,
    __half (*As)[128][40], __half (*Bs)[128][40])
{
    const int tid  = threadIdx.x;
    const int lane = tid & 31;
    const int wid  = tid >> 5;
    const int wm   = wid >> 2;
    const int wn   = wid & 3;

    float acc[4][4][4];
#pragma unroll
    for (int i = 0; i < 4; i++)
#pragma unroll
        for (int j = 0; j < 4; j++)
#pragma unroll
            for (int r = 0; r < 4; r++) acc[i][j][r] = 0.f;

    auto load_stage = [&](int chunk, int buf) {
        const __half* Ar = A + (size_t)m0 * DD + chunk * 32;
        const __half* Br = Bt + (size_t)n0 * DD + chunk * 32;
#pragma unroll
        for (int e = tid; e < 512; e += 256) {
            int row = e >> 2, c = e & 3;
            cp16(&As[buf][row][c * 8], Ar + (size_t)row * DD + c * 8, true);
        }
#pragma unroll
        for (int e = tid; e < 512; e += 256) {
            int row = e >> 2, c = e & 3;
            cp16(&Bs[buf][row][c * 8], Br + (size_t)row * DD + c * 8, true);
        }
        asm volatile("cp.async.commit_group;\n");
    };

    load_stage(0, 0);
    asm volatile("cp.async.wait_group 0;\n");
    __syncthreads();

    for (int chunk = 0; chunk < 32; chunk++) {
        int buf = chunk & 1;
        if (chunk + 1 < 32) load_stage(chunk + 1, buf ^ 1);
        else asm volatile("cp.async.commit_group;\n");
#pragma unroll
        for (int ks = 0; ks < 2; ks++) {
            const int kb   = (ks << 4) + ((lane & 3) << 1);
            const int mrow = (wm << 6) + (lane >> 2);
            const int ncol = (wn << 5) + (lane >> 2);
            uint32_t af[4][4], bf[4][2];
#pragma unroll
            for (int mi = 0; mi < 4; mi++) {
                af[mi][0] = *(const uint32_t*)&As[buf][mrow + mi*16    ][kb    ];
                af[mi][1] = *(const uint32_t*)&As[buf][mrow + mi*16 + 8][kb    ];
                af[mi][2] = *(const uint32_t*)&As[buf][mrow + mi*16    ][kb + 8];
                af[mi][3] = *(const uint32_t*)&As[buf][mrow + mi*16 + 8][kb + 8];
            }
#pragma unroll
            for (int ni = 0; ni < 4; ni++) {
                bf[ni][0] = *(const uint32_t*)&Bs[buf][ncol + ni*8][kb    ];
                bf[ni][1] = *(const uint32_t*)&Bs[buf][ncol + ni*8][kb + 8];
            }
#pragma unroll
            for (int mi = 0; mi < 4; mi++)
#pragma unroll
                for (int ni = 0; ni < 4; ni++)
                    asm volatile(
                        "mma.sync.aligned.m16n8k16.row.col.f32.f16.f16.f32 "
                        "{%0,%1,%2,%3}, {%4,%5,%6,%7}, {%8,%9}, {%0,%1,%2,%3};\n"
                        : "+f"(acc[mi][ni][0]), "+f"(acc[mi][ni][1]),
                          "+f"(acc[mi][ni][2]), "+f"(acc[mi][ni][3])
                        : "r"(af[mi][0]), "r"(af[mi][1]), "r"(af[mi][2]), "r"(af[mi][3]),
                          "r"(bf[ni][0]), "r"(bf[ni][1]));
        }
        asm volatile("cp.async.wait_group 0;\n");
        __syncthreads();
    }

    // epilogue: float2 stores (n, n+1 adjacent); N=1024, no predicates
#pragma unroll
    for (int mi = 0; mi < 4; mi++) {
        int m = m0 + (wm << 6) + mi*16 + (lane >> 2);
#pragma unroll
        for (int ni = 0; ni < 4; ni++) {
            int n = n0 + (wn << 5) + ni*8 + ((lane & 3) << 1);
            float2 v0, v1;
            v0.x = apply_epi(acc[mi][ni][0], epi, nullptr, n);
            v0.y = apply_epi(acc[mi][ni][1], epi, nullptr, n + 1);
            v1.x = apply_epi(acc[mi][ni][2], epi, nullptr, n);
            v1.y = apply_epi(acc[mi][ni][3], epi, nullptr, n + 1);
            *(float2*)(C + (size_t)m * DD + n) = v0;
            *(float2*)(C + (size_t)(m + 8) * DD + n) = v1;
        }
    }
}

struct HArgs { const __half* A[4]; const __half* Bt[4]; float* C[4]; int epi[4]; };

__global__ __launch_bounds__(256) void hgemm_batch(HArgs a)
{
    __shared__ __half As[2][128][40];
    __shared__ __half Bs[2][128][40];
    int z = blockIdx.z;
    hgemm_body(a.A[z], a.Bt[z], a.C[z], a.epi[z],
               blockIdx.y << 7, blockIdx.x << 7, As, Bs);
}

__global__ __launch_bounds__(256) void hgemm(
    const __half* __restrict__ A, const __half* __restrict__ Bt,
    float* __restrict__ C, int epi)
{
    __shared__ __half As[2][128][40];
    __shared__ __half Bs[2][128][40];
    hgemm_body(A, Bt, C, epi, blockIdx.y << 7, blockIdx.x << 7, As, Bs);
}

// ---------------- mma.sync tf32 GEMM (small shapes: W1, dw1, dw2) -----------
__device__ __forceinline__ void gemm_body(
    const float* __restrict__ A, const float* __restrict__ B,
    float* __restrict__ C, int N, int Kd, const float* __restrict__ bias,
    int epi, int m0, int n0,
    float (*As)[128][20], float (*Bs)[16][136])
{
    const int tid  = threadIdx.x;
    const int lane = tid & 31;
    const int wid  = tid >> 5;
    const int wm   = wid >> 2;
    const int wn   = wid & 3;

    float acc[4][4][4];
#pragma unroll
    for (int i = 0; i < 4; i++)
#pragma unroll
        for (int j = 0; j < 4; j++)
#pragma unroll
            for (int r = 0; r < 4; r++) acc[i][j][r] = 0.f;

    const int arow = tid >> 2;
    const int acol = (tid & 3) << 2;
    const int brow = tid >> 5;
    const int bcol = (tid & 31) << 2;
    const bool bpred = (n0 + bcol) < N;

    auto load_chunk = [&](int k0, int buf) {
#pragma unroll
        for (int r = 0; r < 2; r++) {
            int mr = arow + (r << 6);
            cp16(&As[buf][mr][acol], A + (size_t)(m0 + mr) * Kd + k0 + acol, true);
        }
#pragma unroll
        for (int r = 0; r < 2; r++) {
            int kr = brow + (r << 3);
            cp16(&Bs[buf][kr][bcol], B + (size_t)(k0 + kr) * N + n0 + bcol, bpred);
        }
        asm volatile("cp.async.commit_group;\n");
    };

    auto compute = [&](int buf) {
#pragma unroll
        for (int ks = 0; ks < 2; ks++) {
            const int kb   = (ks << 3) + (lane & 3);
            const int mrow = (wm << 6) + (lane >> 2);
            const int ncol = (wn << 5) + (lane >> 2);
            uint32_t af[4][4], bf[4][2];
#pragma unroll
            for (int mi = 0; mi < 4; mi++) {
                af[mi][0] = cvt_tf32(As[buf][mrow + mi*16    ][kb    ]);
                af[mi][1] = cvt_tf32(As[buf][mrow + mi*16 + 8][kb    ]);
                af[mi][2] = cvt_tf32(As[buf][mrow + mi*16    ][kb + 4]);
                af[mi][3] = cvt_tf32(As[buf][mrow + mi*16 + 8][kb + 4]);
            }
#pragma unroll
            for (int ni = 0; ni < 4; ni++) {
                bf[ni][0] = cvt_tf32(Bs[buf][kb    ][ncol + ni*8]);
                bf[ni][1] = cvt_tf32(Bs[buf][kb + 4][ncol + ni*8]);
            }
#pragma unroll
            for (int mi = 0; mi < 4; mi++)
#pragma unroll
                for (int ni = 0; ni < 4; ni++)
                    asm volatile(
                        "mma.sync.aligned.m16n8k8.row.col.f32.tf32.tf32.f32 "
                        "{%0,%1,%2,%3}, {%4,%5,%6,%7}, {%8,%9}, {%0,%1,%2,%3};\n"
                        : "+f"(acc[mi][ni][0]), "+f"(acc[mi][ni][1]),
                          "+f"(acc[mi][ni][2]), "+f"(acc[mi][ni][3])
                        : "r"(af[mi][0]), "r"(af[mi][1]), "r"(af[mi][2]), "r"(af[mi][3]),
                          "r"(bf[ni][0]), "r"(bf[ni][1]));
        }
    };

    load_chunk(0, 0);
    asm volatile("cp.async.wait_group 0;\n");
    __syncthreads();

    const int nK = Kd >> 4;
    for (int kc = 0; kc < nK; kc++) {
        int buf = kc & 1;
        if (kc + 1 < nK) load_chunk((kc + 1) << 4, buf ^ 1);
        else asm volatile("cp.async.commit_group;\n");
        compute(buf);
        asm volatile("cp.async.wait_group 0;\n");
        __syncthreads();
    }

#pragma unroll
    for (int mi = 0; mi < 4; mi++) {
        int m = m0 + (wm << 6) + mi*16 + (lane >> 2);
#pragma unroll
        for (int ni = 0; ni < 4; ni++) {
            int n = n0 + (wn << 5) + ni*8 + ((lane & 3) << 1);
            if (n < N) {
                float2 v0, v1;
                v0.x = apply_epi(acc[mi][ni][0], epi, bias, n);
                v0.y = apply_epi(acc[mi][ni][1], epi, bias, n + 1);
                v1.x = apply_epi(acc[mi][ni][2], epi, bias, n);
                v1.y = apply_epi(acc[mi][ni][3], epi, bias, n + 1);
                *(float2*)(C + (size_t)m * N + n) = v0;
                *(float2*)(C + (size_t)(m + 8) * N + n) = v1;
            }
        }
    }
}

template<int EPI>
__global__ __launch_bounds__(256) void gemm_tf32(
    const float* __restrict__ A, const float* __restrict__ B,
    float* __restrict__ C, int M, int N, int Kd, const float* __restrict__ bias)
{
    __shared__ float As[2][128][20];
    __shared__ float Bs[2][16][136];
    int n0 = blockIdx.x << 7;
    if (n0 >= N) return;
    gemm_body(A, B, C, N, Kd, bias, EPI, blockIdx.y << 7, n0, As, Bs);
}

// ---------------- kernel 3: 5-branch LoRA mix (fp16 outputs) ----------------
__global__ __launch_bounds__(320) void branch_mix(
    const float* __restrict__ x,
    const float* __restrict__ xxx, const float* __restrict__ W2,
    const float* __restrict__ tmw, const float* __restrict__ tmk,
    const float* __restrict__ tmv, const float* __restrict__ tmr,
    const float* __restrict__ tmg,
    float* __restrict__ xw,
    __half* __restrict__ xkh, __half* __restrict__ xvh,
    __half* __restrict__ xrh, __half* __restrict__ xgh)
{
    __shared__ float sxxxT[160][20];
    __shared__ float sx [16][64];
    __shared__ float sxx[16][64];

    const int tid = threadIdx.x;
    const int t0  = blockIdx.x * 16;
    const int d0  = blockIdx.y * 64;

    for (int e = tid; e < 16 * 160; e += 320) {
        int tok = e / 160, c = e - tok * 160;
        sxxxT[c][tok] = xxx[(size_t)(t0 + tok) * 160 + c];
    }
    for (int e = tid; e < 16 * 64; e += 320) {
        int t = e >> 6, c = e & 63;
        size_t gi = (size_t)(t0 + t) * DD + d0 + c;
        float xv_ = x[gi];
        float prev = (((t0 + t) & (TT - 1)) == 0) ? 0.f : x[gi - DD];
        sx [t][c] = xv_;
        sxx[t][c] = prev - xv_;
    }
    __syncthreads();

    const int f  = tid >> 6;
    const int dl = tid & 63;
    const int d  = d0 + dl;

    float4 macc[4];
#pragma unroll
    for (int g = 0; g < 4; g++) macc[g] = make_float4(0.f, 0.f, 0.f, 0.f);

    const float* W2f = W2 + (size_t)(f * 32) * DD + d;
#pragma unroll 8
    for (int i = 0; i < 32; i++) {
        float wv = W2f[(size_t)i * DD];
        const float4* xr4 = (const float4*)&sxxxT[f * 32 + i][0];
#pragma unroll
        for (int g = 0; g < 4; g++) {
            float4 xv4 = xr4[g];
            macc[g].x += xv4.x * wv; macc[g].y += xv4.y * wv;
            macc[g].z += xv4.z * wv; macc[g].w += xv4.w * wv;
        }
    }
    float m[16];
#pragma unroll
    for (int g = 0; g < 4; g++) {
        m[g*4+0] = macc[g].x; m[g*4+1] = macc[g].y;
        m[g*4+2] = macc[g].z; m[g*4+3] = macc[g].w;
    }

    if (f == 0) {
        float tmv_ = tmw[d];
#pragma unroll
        for (int tok = 0; tok < 16; tok++) {
            float val = sx[tok][dl] + sxx[tok][dl] * (tmv_ + m[tok]);
            xw[(size_t)(t0 + tok) * DD + d] = val;
        }
    } else {
        const float* tmsel = (f == 1) ? tmk : (f == 2) ? tmv : (f == 3) ? tmr : tmg;
        __half* osel = (f == 1) ? xkh : (f == 2) ? xvh : (f == 3) ? xrh : xgh;
        float tmv_ = tmsel[d];
#pragma unroll
        for (int tok = 0; tok < 16; tok++) {
            float val = sx[tok][dl] + sxx[tok][dl] * (tmv_ + m[tok]);
            osel[(size_t)(t0 + tok) * DD + d] = __float2half_rn(val);
        }
    }
}

// ---------------- WKV pass 1: per-chunk intra work + summaries --------------
#define PAD 4
__global__ __launch_bounds__(256) void wkv_chunk(
    const float* __restrict__ r, const float* __restrict__ k,
    const float* __restrict__ v, const float* __restrict__ w,
    const float* __restrict__ u,
    float* __restrict__ rw, float* __restrict__ att,
    float* __restrict__ wkvc, float* __restrict__ expws)
{
    __shared__ float sr [SCH][KK + PAD];
    __shared__ float sk [SCH][KK + PAD];
    __shared__ float sv [SCH][KK + PAD];
    __shared__ float swl[SCH][KK + PAD];
    __shared__ float swc[SCH][KK + PAD];
    __shared__ float soff[KK];
    __shared__ float sdiag[SCH];
    float* sA = &swc[0][0];

    int tid = threadIdx.x;
    int bid = blockIdx.x;
    int n = bid & (NCH - 1);
    int h = (bid / NCH) & (HH - 1);
    int b = bid / (NCH * HH);
    size_t base = ((size_t)(b * TT + n * SCH)) * DD + h * KK;

    for (int e = tid; e < SCH * KK; e += 256) {
        int t = e >> 6, c = e & 63;
        size_t gi = base + (size_t)t * DD + c;
        sr [t][c] = r[gi];
        sk [t][c] = k[gi];
        sv [t][c] = v[gi];
        swl[t][c] = fmaxf(w[gi], LOGMIN);
    }
    __syncthreads();
    if (tid < KK) {
        float c = 0.f;
        for (int t = 0; t < SCH; t++) { c += swl[t][tid]; swc[t][tid] = c; }
        expws[(size_t)bid * KK + tid] = expf(c);
        soff[tid] = swc[16][tid] - swl[16][tid];
    }
    __syncthreads();
    if (tid < SCH) {
        float acc = 0.f;
        const float4* rp = (const float4*)&sr[tid][0];
        const float4* kp = (const float4*)&sk[tid][0];
        const float4* up = (const float4*)(u + h * KK);
        for (int c = 0; c < 16; c++) {
            float4 a = rp[c], bb = kp[c], uu = up[c];
            acc += a.x*uu.x*bb.x + a.y*uu.y*bb.y + a.z*uu.z*bb.z + a.w*uu.w*bb.w;
        }
        sdiag[tid] = acc;
    }
    __syncthreads();
    for (int e = tid; e < SCH * KK; e += 256) {
        int t = e >> 6, c = e & 63;
        float wl = swl[t][c], wc = swc[t][c];
        float shft = wc - wl;
        float off  = soff[c];
        float ws   = swc[SCH - 1][c];
        float rv = sr[t][c], kv = sk[t][c];
        rw[base + (size_t)t * DD + c] = rv * expf(shft);
        sr [t][c] = rv * expf(shft - off);
        sk [t][c] = kv * expf(off - wc);
        swl[t][c] = kv * expf(ws - wc);
    }
    __syncthreads();
    for (int e = tid; e < SCH * SCH; e += 256) {
        int i = e >> 5, j = e & 31;
        float acc = 0.f;
        if (i > j) {
            const float4* rp = (const float4*)&sr[i][0];
            const float4* kp = (const float4*)&sk[j][0];
#pragma unroll 4
            for (int c = 0; c < 16; c++) {
                float4 a = rp[c], bb = kp[c];
                acc += a.x*bb.x + a.y*bb.y + a.z*bb.z + a.w*bb.w;
            }
        } else if (i == j) acc = sdiag[i];
        sA[e] = acc;
    }
    __syncthreads();
    for (int item = tid; item < SCH * 16; item += 256) {
        int t = item >> 4, v4 = item & 15;
        float4 acc = {0.f, 0.f, 0.f, 0.f};
        const float* arow = sA + t * SCH;
        for (int j = 0; j <= t; j++) {
            float a = arow[j];
            float4 vv = *(const float4*)&sv[j][v4 << 2];
            acc.x += a * vv.x; acc.y += a * vv.y;
            acc.z += a * vv.z; acc.w += a * vv.w;
        }
        *(float4*)(att + base + (size_t)t * DD + (v4 << 2)) = acc;
    }
    {
        int c0 = (tid >> 4) << 2;
        int v0 = (tid & 15) << 2;
        float acc[4][4];
#pragma unroll
        for (int i = 0; i < 4; i++)
#pragma unroll
            for (int j = 0; j < 4; j++) acc[i][j] = 0.f;
        for (int t = 0; t < SCH; t++) {
            float4 kw = *(const float4*)&swl[t][c0];
            float4 vv = *(const float4*)&sv[t][v0];
            float ka[4] = {kw.x, kw.y, kw.z, kw.w};
            float va[4] = {vv.x, vv.y, vv.z, vv.w};
#pragma unroll
            for (int i = 0; i < 4; i++)
#pragma unroll
                for (int j = 0; j < 4; j++) acc[i][j] += ka[i] * va[j];
        }
        size_t ob = (size_t)bid * (KK * KK);
#pragma unroll
        for (int i = 0; i < 4; i++) {
            float4 o4; o4.x = acc[i][0]; o4.y = acc[i][1];
            o4.z = acc[i][2]; o4.w = acc[i][3];
            *(float4*)(wkvc + ob + (size_t)(c0 + i) * KK + v0) = o4;
        }
    }
}

// ---------------- WKV pass 2: serial scan over chunks -----------------------
__global__ __launch_bounds__(1024) void wkv_scan(
    const float* __restrict__ wkvc, const float* __restrict__ expws,
    float* __restrict__ states)
{
    int bh = blockIdx.x;
    int tid = threadIdx.x;
    int c  = tid >> 4;
    int v0 = (tid & 15) << 2;
    float s0 = 0.f, s1 = 0.f, s2 = 0.f, s3 = 0.f;
    size_t eb = (size_t)bh * NCH * KK;
    size_t sb = (size_t)bh * NCH * KK * KK + (size_t)c * KK + v0;
    for (int n = 0; n < NCH; n++) {
        float wd = expws[eb + (size_t)n * KK + c];
        size_t o = sb + (size_t)n * KK * KK;
        float4 st; st.x = s0; st.y = s1; st.z = s2; st.w = s3;
        *(float4*)(states + o) = st;
        float4 wc4 = *(const float4*)(wkvc + o);
        s0 = s0 * wd + wc4.x; s1 = s1 * wd + wc4.y;
        s2 = s2 * wd + wc4.z; s3 = s3 * wd + wc4.w;
    }
}

// ---------------- WKV pass 3: apply carried state ---------------------------
__global__ __launch_bounds__(256) void wkv_state_out(
    const float* __restrict__ rw, const float* __restrict__ states,
    float* __restrict__ att)
{
    __shared__ float sst[KK][KK];
    __shared__ float srw[SCH][KK];
    int tid = threadIdx.x, bid = blockIdx.x;
    int n = bid & (NCH - 1);
    int h = (bid / NCH) & (HH - 1);
    int b = bid / (NCH * HH);
    size_t base = ((size_t)(b * TT + n * SCH)) * DD + h * KK;
    size_t stb = (size_t)bid * (KK * KK);
    for (int e = tid; e < KK * KK / 4; e += 256)
        ((float4*)&sst[0][0])[e] = ((const float4*)(states + stb))[e];
    for (int e = tid; e < SCH * KK / 4; e += 256) {
        int t = e >> 4, c4 = e & 15;
        ((float4*)&srw[t][0])[c4] =
            *(const float4*)(rw + base + (size_t)t * DD + (c4 << 2));
    }
    __syncthreads();
    int t0 = (tid >> 4) << 1;
    int v0 = (tid & 15) << 2;
    float4 acc0 = {0.f,0.f,0.f,0.f}, acc1 = {0.f,0.f,0.f,0.f};
#pragma unroll 4
    for (int c = 0; c < KK; c++) {
        float4 sv4 = *(const float4*)&sst[c][v0];
        float r0 = srw[t0][c], r1 = srw[t0 + 1][c];
        acc0.x += r0 * sv4.x; acc0.y += r0 * sv4.y;
        acc0.z += r0 * sv4.z; acc0.w += r0 * sv4.w;
        acc1.x += r1 * sv4.x; acc1.y += r1 * sv4.y;
        acc1.z += r1 * sv4.z; acc1.w += r1 * sv4.w;
    }
    float4* o0 = (float4*)(att + base + (size_t)t0 * DD + v0);
    float4* o1 = (float4*)(att + base + (size_t)(t0 + 1) * DD + v0);
    float4 p0 = *o0, p1 = *o1;
    p0.x += acc0.x; p0.y += acc0.y; p0.z += acc0.z; p0.w += acc0.w;
    p1.x += acc1.x; p1.y += acc1.y; p1.z += acc1.z; p1.w += acc1.w;
    *o0 = p0; *o1 = p1;
}

// ---------------- group-norm (per head) + gate -> fp16 ----------------------
__global__ __launch_bounds__(256) void gnorm_gate(
    const float* __restrict__ att, const float* __restrict__ gate,
    const float* __restrict__ lnw, const float* __restrict__ lnb,
    __half* __restrict__ y)
{
    int token = blockIdx.x, tid = threadIdx.x;
    size_t base = (size_t)token * DD + tid * 4;
    float4 v4 = *(const float4*)(att + base);
    float s  = v4.x + v4.y + v4.z + v4.w;
    float ss = v4.x * v4.x + v4.y * v4.y + v4.z * v4.z + v4.w * v4.w;
#pragma unroll
    for (int o = 1; o < 16; o <<= 1) {
        s  += __shfl_xor_sync(0xffffffffu, s,  o);
        ss += __shfl_xor_sync(0xffffffffu, ss, o);
    }
    float mean = s * (1.f / KK);
    float var  = ss * (1.f / KK) - mean * mean;
    float rstd = rsqrtf(var + LN_EPS);
    float4 g4 = *(const float4*)(gate + base);
    float4 w4 = *(const float4*)(lnw + tid * 4);
    float4 b4 = *(const float4*)(lnb + tid * 4);
    __half2 h0 = __floats2half2_rn(((v4.x - mean) * rstd * w4.x + b4.x) * g4.x,
                                   ((v4.y - mean) * rstd * w4.y + b4.y) * g4.y);
    __half2 h1 = __floats2half2_rn(((v4.z - mean) * rstd * w4.z + b4.z) * g4.z,
                                   ((v4.w - mean) * rstd * w4.w + b4.w) * g4.w);
    *(__half2*)(y + base)     = h0;
    *(__half2*)(y + base + 2) = h1;
}

// ---------------- launch ----------------------------------------------------
extern "C" void kernel_launch(void* const* d_in, const int* in_sizes, int n_in,
                              void* d_out, int out_size)
{
    const float* x     = (const float*)d_in[0];
    const float* tmx   = (const float*)d_in[1];
    const float* tmw   = (const float*)d_in[2];
    const float* tmk   = (const float*)d_in[3];
    const float* tmv   = (const float*)d_in[4];
    const float* tmr   = (const float*)d_in[5];
    const float* tmg   = (const float*)d_in[6];
    const float* w1    = (const float*)d_in[7];
    const float* w2    = (const float*)d_in[8];
    const float* tdec  = (const float*)d_in[9];
    const float* dw1   = (const float*)d_in[10];
    const float* dw2   = (const float*)d_in[11];
    const float* faaaa = (const float*)d_in[12];
    const float* Wr    = (const float*)d_in[13];
    const float* Wk    = (const float*)d_in[14];
    const float* Wv    = (const float*)d_in[15];
    const float* Wg    = (const float*)d_in[16];
    const float* Wo    = (const float*)d_in[17];
    const float* lnw   = (const float*)d_in[18];
    const float* lnb   = (const float*)d_in[19];
    float* out = (float*)d_out;

    float *p_xmix, *p_xxx, *p_xw, *p_r, *p_k, *p_v, *p_gate, *p_w, *p_t1;
    float *p_rw, *p_att, *p_wkvc, *p_states, *p_expws;
    __half *p_xrh, *p_xkh, *p_xvh, *p_xgh, *p_ynh;
    __half *p_WrH, *p_WkH, *p_WvH, *p_WgH, *p_WoH;
    cudaGetSymbolAddress((void**)&p_xmix,  g_xmix);
    cudaGetSymbolAddress((void**)&p_xxx,   g_xxx);
    cudaGetSymbolAddress((void**)&p_xw,    g_xw);
    cudaGetSymbolAddress((void**)&p_r,     g_r);
    cudaGetSymbolAddress((void**)&p_k,     g_k);
    cudaGetSymbolAddress((void**)&p_v,     g_v);
    cudaGetSymbolAddress((void**)&p_gate,  g_gate);
    cudaGetSymbolAddress((void**)&p_w,     g_w);
    cudaGetSymbolAddress((void**)&p_t1,    g_t1);
    cudaGetSymbolAddress((void**)&p_rw,    g_rw);
    cudaGetSymbolAddress((void**)&p_att,   g_att);
    cudaGetSymbolAddress((void**)&p_wkvc,  g_wkvc);
    cudaGetSymbolAddress((void**)&p_states,g_states);
    cudaGetSymbolAddress((void**)&p_expws, g_expws);
    cudaGetSymbolAddress((void**)&p_xrh,   g_xrh);
    cudaGetSymbolAddress((void**)&p_xkh,   g_xkh);
    cudaGetSymbolAddress((void**)&p_xvh,   g_xvh);
    cudaGetSymbolAddress((void**)&p_xgh,   g_xgh);
    cudaGetSymbolAddress((void**)&p_ynh,   g_ynh);
    cudaGetSymbolAddress((void**)&p_WrH,   g_WrH);
    cudaGetSymbolAddress((void**)&p_WkH,   g_WkH);
    cudaGetSymbolAddress((void**)&p_WvH,   g_WvH);
    cudaGetSymbolAddress((void**)&p_WgH,   g_WgH);
    cudaGetSymbolAddress((void**)&p_WoH,   g_WoH);

    // 0. repack big weights -> [N,K] fp16
    RepHArgs rp;
    rp.src[0] = Wr; rp.dst[0] = p_WrH;
    rp.src[1] = Wk; rp.dst[1] = p_WkH;
    rp.src[2] = Wv; rp.dst[2] = p_WvH;
    rp.src[3] = Wg; rp.dst[3] = p_WgH;
    rp.src[4] = Wo; rp.dst[4] = p_WoH;
    repack_wh<<<dim3(32, 32, 5), 256>>>(rp);
    // 1. token shift + mix input
    prep_kernel<<<(BT * DD) / 256, 256>>>(x, tmx, p_xmix);
    // 2. xxx = tanh(xmix @ W1)   (tf32 path, N=160)
    gemm_tf32<1><<<dim3(2, 64), 256>>>(p_xmix, w1, p_xxx, BT, 160, DD, nullptr);
    // 3. five branch inputs (xw float; xk/xv/xr/xg fp16)
    branch_mix<<<dim3(BT / 16, DD / 64), 320>>>(x, p_xxx, w2,
                                                tmw, tmk, tmv, tmr, tmg,
                                                p_xw, p_xkh, p_xvh, p_xrh, p_xgh);
    // 4. fp16 tensor-core batch: r/k/v projections + gate (silu)
    HArgs ha;
    ha.A[0] = p_xrh; ha.Bt[0] = p_WrH; ha.C[0] = p_r;    ha.epi[0] = 0;
    ha.A[1] = p_xkh; ha.Bt[1] = p_WkH; ha.C[1] = p_k;    ha.epi[1] = 0;
    ha.A[2] = p_xvh; ha.Bt[2] = p_WvH; ha.C[2] = p_v;    ha.epi[2] = 0;
    ha.A[3] = p_xgh; ha.Bt[3] = p_WgH; ha.C[3] = p_gate; ha.epi[3] = 2;
    hgemm_batch<<<dim3(8, 64, 4), 256>>>(ha);
    // 5. decay LoRA (tf32 path): t1 = tanh(xw @ dw1); w = -exp(tdec + t1 @ dw2)
    gemm_tf32<1><<<dim3(1, 64), 256>>>(p_xw, dw1, p_t1, BT, 64, DD, nullptr);
    gemm_tf32<3><<<dim3(8, 64), 256>>>(p_t1, dw2, p_w, BT, DD, 64, tdec);
    // 6. WKV
    wkv_chunk<<<NBH * NCH, 256>>>(p_r, p_k, p_v, p_w, faaaa,
                                  p_rw, p_att, p_wkvc, p_expws);
    wkv_scan<<<NBH, 1024>>>(p_wkvc, p_expws, p_states);
    wkv_state_out<<<NBH * NCH, 256>>>(p_rw, p_states, p_att);
    // 7. group-norm + gate (fp16), then fp16 output projection
    gnorm_gate<<<BT, 256>>>(p_att, p_gate, lnw, lnb, p_ynh);
    hgemm<<<dim3(8, 64), 256>>>(p_ynh, p_WoH, out, 0);
}

// round 16
// speedup vs baseline: 1.4258x; 1.0740x over previous
#include <cuda_runtime.h>
#include <cuda_fp16.h>
#include <cuda_bf16.h>
#include <cstdint>
#include <math.h>

#define BB 4
#define TT 2048
#define DD 1024
#define HH 16
#define KK 64
#define BT (BB*TT)          /* 8192 tokens */
#define SCH 32              /* chunk length (numerically safe in fp32) */
#define NCH (TT/SCH)        /* 64 chunks per sequence */
#define NBH (BB*HH)         /* 64 (batch,head) pairs */
#define LOGMIN (-5.2983174f) /* log(0.005) */
#define LN_EPS 6.4e-4f       /* 1e-5 * 8^2 */

// ---------------- scratch (static device arrays; no runtime allocation) ----
static __device__ float g_xmix [BT*DD];
static __device__ float g_xw   [BT*DD];
static __device__ float g_r    [BT*DD];
static __device__ float g_k    [BT*DD];
static __device__ float g_v    [BT*DD];
static __device__ float g_gate [BT*DD];
static __device__ float g_w    [BT*DD];
static __device__ float g_t1   [BT*64];
static __device__ float g_rw   [BT*DD];
static __device__ float g_att  [BT*DD];
static __device__ float g_wkvc [NBH*NCH*KK*KK];
static __device__ float g_states[NBH*NCH*KK*KK];
static __device__ float g_expws[NBH*NCH*KK];
// fp16 operands for tensor-core GEMMs
static __device__ __half g_xxxh[BT*160];
static __device__ __half g_xrh [BT*DD];
static __device__ __half g_xkh [BT*DD];
static __device__ __half g_xvh [BT*DD];
static __device__ __half g_xgh [BT*DD];
static __device__ __half g_ynh [BT*DD];
static __device__ __half g_WrH [DD*DD];   // transposed [N,K]
static __device__ __half g_WkH [DD*DD];
static __device__ __half g_WvH [DD*DD];
static __device__ __half g_WgH [DD*DD];
static __device__ __half g_WoH [DD*DD];
static __device__ __half g_W2H [5*DD*32]; // [f][d][i]  (K-major per branch)

__device__ __forceinline__ uint32_t cvt_tf32(float x) {
    uint32_t r;
    asm("cvt.rna.tf32.f32 %0, %1;" : "=r"(r) : "f"(x));
    return r;
}

// ---------------- kernel 0a: transpose + fp16-round the 5 big weights ------
struct RepHArgs { const float* src[5]; __half* dst[5]; };

__global__ __launch_bounds__(256) void repack_wh(RepHArgs a)
{
    __shared__ float tile[32][33];
    int z = blockIdx.z;
    const float* W = a.src[z];
    __half* WT = a.dst[z];
    int c0 = blockIdx.x * 32, r0 = blockIdx.y * 32;
    int tx = threadIdx.x & 31, ty = threadIdx.x >> 5;
#pragma unroll
    for (int i = 0; i < 32; i += 8)
        tile[ty + i][tx] = W[(size_t)(r0 + ty + i) * DD + c0 + tx];
    __syncthreads();
#pragma unroll
    for (int i = 0; i < 32; i += 8)
        WT[(size_t)(c0 + ty + i) * DD + r0 + tx] = __float2half_rn(tile[tx][ty + i]);
}

// ---------------- kernel 0b: repack w2 [5,32,1024] -> fp16 [5,1024,32] ------
__global__ __launch_bounds__(256) void repack_w2(const float* __restrict__ w2,
                                                 __half* __restrict__ W2H)
{
    int o = blockIdx.x * 256 + threadIdx.x;   // total 5*1024*32 = 163840
    if (o < 5 * DD * 32) {
        int i = o & 31;
        int d = (o >> 5) & (DD - 1);
        int f = o >> 15;
        W2H[o] = __float2half_rn(w2[(size_t)(f * 32 + i) * DD + d]);
    }
}

// ---------------- kernel 1: token shift + mix input ------------------------
__global__ void prep_kernel(const float* __restrict__ x, const float* __restrict__ tmx,
                            float* __restrict__ xmix)
{
    size_t idx = (size_t)blockIdx.x * 256 + threadIdx.x;
    int d = (int)(idx & (DD - 1));
    int t = (int)((idx >> 10) & (TT - 1));   // DD = 2^10
    float xv = x[idx];
    float prev = (t == 0) ? 0.f : x[idx - DD];
    float xxv = prev - xv;
    xmix[idx] = xv + xxv * tmx[d];
}

// ---------------- cp.async helper -------------------------------------------
__device__ __forceinline__ void cp16(void* smem_dst, const void* gmem_src, bool pred) {
    uint32_t saddr = (uint32_t)__cvta_generic_to_shared(smem_dst);
    if (pred)
        asm volatile("cp.async.cg.shared.global [%0], [%1], 16;\n"
                     :: "r"(saddr), "l"(gmem_src));
    else
        asm volatile("cp.async.cg.shared.global [%0], [%1], 16, 0;\n"
                     :: "r"(saddr), "l"(gmem_src));
}

// epi: 0 none, 1 tanh, 2 silu, 3 -exp(bias[n]+v), 4 tanh->fp16
__device__ __forceinline__ float apply_epi(float v, int epi, const float* bias, int n) {
    if (epi == 1) return tanhf(v);
    if (epi == 2) return v * (1.f / (1.f + expf(-v)));
    if (epi == 3) return -expf(bias[n] + v);
    return v;
}

// ================= fp16 tensor-core GEMM ====================================
__device__ __forceinline__ void hgemm_body(
    const __half* __restrict__ A, const __half* __restrict__ Bt,
    float* __restrict__ C, int epi, int m0, int n0,
    __half (*As)[128][40], __half (*Bs)[128][40])
{
    const int tid  = threadIdx.x;
    const int lane = tid & 31;
    const int wid  = tid >> 5;
    const int wm   = wid >> 2;
    const int wn   = wid & 3;

    float acc[4][4][4];
#pragma unroll
    for (int i = 0; i < 4; i++)
#pragma unroll
        for (int j = 0; j < 4; j++)
#pragma unroll
            for (int r = 0; r < 4; r++) acc[i][j][r] = 0.f;

    auto load_stage = [&](int chunk, int buf) {
        const __half* Ar = A + (size_t)m0 * DD + chunk * 32;
        const __half* Br = Bt + (size_t)n0 * DD + chunk * 32;
#pragma unroll
        for (int e = tid; e < 512; e += 256) {
            int row = e >> 2, c = e & 3;
            cp16(&As[buf][row][c * 8], Ar + (size_t)row * DD + c * 8, true);
        }
#pragma unroll
        for (int e = tid; e < 512; e += 256) {
            int row = e >> 2, c = e & 3;
            cp16(&Bs[buf][row][c * 8], Br + (size_t)row * DD + c * 8, true);
        }
        asm volatile("cp.async.commit_group;\n");
    };

    load_stage(0, 0);
    asm volatile("cp.async.wait_group 0;\n");
    __syncthreads();

    for (int chunk = 0; chunk < 32; chunk++) {
        int buf = chunk & 1;
        if (chunk + 1 < 32) load_stage(chunk + 1, buf ^ 1);
        else asm volatile("cp.async.commit_group;\n");
#pragma unroll
        for (int ks = 0; ks < 2; ks++) {
            const int kb   = (ks << 4) + ((lane & 3) << 1);
            const int mrow = (wm << 6) + (lane >> 2);
            const int ncol = (wn << 5) + (lane >> 2);
            uint32_t af[4][4], bf[4][2];
#pragma unroll
            for (int mi = 0; mi < 4; mi++) {
                af[mi][0] = *(const uint32_t*)&As[buf][mrow + mi*16    ][kb    ];
                af[mi][1] = *(const uint32_t*)&As[buf][mrow + mi*16 + 8][kb    ];
                af[mi][2] = *(const uint32_t*)&As[buf][mrow + mi*16    ][kb + 8];
                af[mi][3] = *(const uint32_t*)&As[buf][mrow + mi*16 + 8][kb + 8];
            }
#pragma unroll
            for (int ni = 0; ni < 4; ni++) {
                bf[ni][0] = *(const uint32_t*)&Bs[buf][ncol + ni*8][kb    ];
                bf[ni][1] = *(const uint32_t*)&Bs[buf][ncol + ni*8][kb + 8];
            }
#pragma unroll
            for (int mi = 0; mi < 4; mi++)
#pragma unroll
                for (int ni = 0; ni < 4; ni++)
                    asm volatile(
                        "mma.sync.aligned.m16n8k16.row.col.f32.f16.f16.f32 "
                        "{%0,%1,%2,%3}, {%4,%5,%6,%7}, {%8,%9}, {%0,%1,%2,%3};\n"
                        : "+f"(acc[mi][ni][0]), "+f"(acc[mi][ni][1]),
                          "+f"(acc[mi][ni][2]), "+f"(acc[mi][ni][3])
                        : "r"(af[mi][0]), "r"(af[mi][1]), "r"(af[mi][2]), "r"(af[mi][3]),
                          "r"(bf[ni][0]), "r"(bf[ni][1]));
        }
        asm volatile("cp.async.wait_group 0;\n");
        __syncthreads();
    }

#pragma unroll
    for (int mi = 0; mi < 4; mi++) {
        int m = m0 + (wm << 6) + mi*16 + (lane >> 2);
#pragma unroll
        for (int ni = 0; ni < 4; ni++) {
            int n = n0 + (wn << 5) + ni*8 + ((lane & 3) << 1);
            float2 v0, v1;
            v0.x = apply_epi(acc[mi][ni][0], epi, nullptr, n);
            v0.y = apply_epi(acc[mi][ni][1], epi, nullptr, n + 1);
            v1.x = apply_epi(acc[mi][ni][2], epi, nullptr, n);
            v1.y = apply_epi(acc[mi][ni][3], epi, nullptr, n + 1);
            *(float2*)(C + (size_t)m * DD + n) = v0;
            *(float2*)(C + (size_t)(m + 8) * DD + n) = v1;
        }
    }
}

struct HArgs { const __half* A[4]; const __half* Bt[4]; float* C[4]; int epi[4]; };

__global__ __launch_bounds__(256) void hgemm_batch(HArgs a)
{
    __shared__ __half As[2][128][40];
    __shared__ __half Bs[2][128][40];
    int z = blockIdx.z;
    hgemm_body(a.A[z], a.Bt[z], a.C[z], a.epi[z],
               blockIdx.y << 7, blockIdx.x << 7, As, Bs);
}

__global__ __launch_bounds__(256) void hgemm(
    const __half* __restrict__ A, const __half* __restrict__ Bt,
    float* __restrict__ C, int epi)
{
    __shared__ __half As[2][128][40];
    __shared__ __half Bs[2][128][40];
    hgemm_body(A, Bt, C, epi, blockIdx.y << 7, blockIdx.x << 7, As, Bs);
}

// ================= fused LoRA-mix GEMM (fp16, K=32) =========================
// For branch f: m = xxx[:, f*32:(f+1)*32] @ W2h[f]  (8192x1024, K=32),
// epilogue: out = x + (xprev - x) * (tm_f + m), written fp32 (f=0) / fp16.
__global__ __launch_bounds__(256) void lora_mix_gemm(
    const __half* __restrict__ xxxh,   // [BT,160]
    const __half* __restrict__ W2H,    // [5][1024][32]
    const float* __restrict__ x,
    const float* __restrict__ tmw, const float* __restrict__ tmk,
    const float* __restrict__ tmv, const float* __restrict__ tmr,
    const float* __restrict__ tmg,
    float* __restrict__ xw,
    __half* __restrict__ xkh, __half* __restrict__ xvh,
    __half* __restrict__ xrh, __half* __restrict__ xgh)
{
    __shared__ __half As[128][40];
    __shared__ __half Bs[128][40];
    const int tid  = threadIdx.x;
    const int lane = tid & 31;
    const int wid  = tid >> 5;
    const int wm   = wid >> 2;
    const int wn   = wid & 3;
    const int f  = blockIdx.z;
    const int m0 = blockIdx.y << 7;
    const int n0 = blockIdx.x << 7;

    {
        const __half* Ar = xxxh + (size_t)m0 * 160 + f * 32;
        const __half* Br = W2H + (size_t)f * DD * 32 + (size_t)n0 * 32;
#pragma unroll
        for (int e = tid; e < 512; e += 256) {
            int row = e >> 2, c = e & 3;
            cp16(&As[row][c * 8], Ar + (size_t)row * 160 + c * 8, true);
        }
#pragma unroll
        for (int e = tid; e < 512; e += 256) {
            int row = e >> 2, c = e & 3;
            cp16(&Bs[row][c * 8], Br + (size_t)row * 32 + c * 8, true);
        }
        asm volatile("cp.async.commit_group;\n");
        asm volatile("cp.async.wait_group 0;\n");
        __syncthreads();
    }

    float acc[4][4][4];
#pragma unroll
    for (int i = 0; i < 4; i++)
#pragma unroll
        for (int j = 0; j < 4; j++)
#pragma unroll
            for (int r = 0; r < 4; r++) acc[i][j][r] = 0.f;

#pragma unroll
    for (int ks = 0; ks < 2; ks++) {
        const int kb   = (ks << 4) + ((lane & 3) << 1);
        const int mrow = (wm << 6) + (lane >> 2);
        const int ncol = (wn << 5) + (lane >> 2);
        uint32_t af[4][4], bf[4][2];
#pragma unroll
        for (int mi = 0; mi < 4; mi++) {
            af[mi][0] = *(const uint32_t*)&As[mrow + mi*16    ][kb    ];
            af[mi][1] = *(const uint32_t*)&As[mrow + mi*16 + 8][kb    ];
            af[mi][2] = *(const uint32_t*)&As[mrow + mi*16    ][kb + 8];
            af[mi][3] = *(const uint32_t*)&As[mrow + mi*16 + 8][kb + 8];
        }
#pragma unroll
        for (int ni = 0; ni < 4; ni++) {
            bf[ni][0] = *(const uint32_t*)&Bs[ncol + ni*8][kb    ];
            bf[ni][1] = *(const uint32_t*)&Bs[ncol + ni*8][kb + 8];
        }
#pragma unroll
        for (int mi = 0; mi < 4; mi++)
#pragma unroll
            for (int ni = 0; ni < 4; ni++)
                asm volatile(
                    "mma.sync.aligned.m16n8k16.row.col.f32.f16.f16.f32 "
                    "{%0,%1,%2,%3}, {%4,%5,%6,%7}, {%8,%9}, {%0,%1,%2,%3};\n"
                    : "+f"(acc[mi][ni][0]), "+f"(acc[mi][ni][1]),
                      "+f"(acc[mi][ni][2]), "+f"(acc[mi][ni][3])
                    : "r"(af[mi][0]), "r"(af[mi][1]), "r"(af[mi][2]), "r"(af[mi][3]),
                      "r"(bf[ni][0]), "r"(bf[ni][1]));
    }

    const float* tmsel = (f == 0) ? tmw : (f == 1) ? tmk :
                         (f == 2) ? tmv : (f == 3) ? tmr : tmg;
    __half* osel = (f == 1) ? xkh : (f == 2) ? xvh :
                   (f == 3) ? xrh : xgh;

#pragma unroll
    for (int mi = 0; mi < 4; mi++) {
        int m = m0 + (wm << 6) + mi*16 + (lane >> 2);
#pragma unroll
        for (int ni = 0; ni < 4; ni++) {
            int n = n0 + (wn << 5) + ni*8 + ((lane & 3) << 1);
            float2 tm2 = *(const float2*)(tmsel + n);
#pragma unroll
            for (int rr = 0; rr < 2; rr++) {
                int mm = m + rr * 8;
                size_t gi = (size_t)mm * DD + n;
                float2 xv2 = *(const float2*)(x + gi);
                float2 xp2;
                if ((mm & (TT - 1)) == 0) { xp2.x = 0.f; xp2.y = 0.f; }
                else xp2 = *(const float2*)(x + gi - DD);
                float v0 = xv2.x + (xp2.x - xv2.x) * (tm2.x + acc[mi][ni][rr*2+0]);
                float v1 = xv2.y + (xp2.y - xv2.y) * (tm2.y + acc[mi][ni][rr*2+1]);
                if (f == 0) {
                    float2 o; o.x = v0; o.y = v1;
                    *(float2*)(xw + gi) = o;
                } else {
                    *(__half2*)(osel + gi) = __floats2half2_rn(v0, v1);
                }
            }
        }
    }
}

// ---------------- mma.sync tf32 GEMM (small shapes: W1, dw1, dw2) -----------
__device__ __forceinline__ void gemm_body(
    const float* __restrict__ A, const float* __restrict__ B,
    float* __restrict__ C, int N, int Kd, const float* __restrict__ bias,
    int epi, int m0, int n0,
    float (*As)[128][20], float (*Bs)[16][136])
{
    const int tid  = threadIdx.x;
    const int lane = tid & 31;
    const int wid  = tid >> 5;
    const int wm   = wid >> 2;
    const int wn   = wid & 3;

    float acc[4][4][4];
#pragma unroll
    for (int i = 0; i < 4; i++)
#pragma unroll
        for (int j = 0; j < 4; j++)
#pragma unroll
            for (int r = 0; r < 4; r++) acc[i][j][r] = 0.f;

    const int arow = tid >> 2;
    const int acol = (tid & 3) << 2;
    const int brow = tid >> 5;
    const int bcol = (tid & 31) << 2;
    const bool bpred = (n0 + bcol) < N;

    auto load_chunk = [&](int k0, int buf) {
#pragma unroll
        for (int r = 0; r < 2; r++) {
            int mr = arow + (r << 6);
            cp16(&As[buf][mr][acol], A + (size_t)(m0 + mr) * Kd + k0 + acol, true);
        }
#pragma unroll
        for (int r = 0; r < 2; r++) {
            int kr = brow + (r << 3);
            cp16(&Bs[buf][kr][bcol], B + (size_t)(k0 + kr) * N + n0 + bcol, bpred);
        }
        asm volatile("cp.async.commit_group;\n");
    };

    auto compute = [&](int buf) {
#pragma unroll
        for (int ks = 0; ks < 2; ks++) {
            const int kb   = (ks << 3) + (lane & 3);
            const int mrow = (wm << 6) + (lane >> 2);
            const int ncol = (wn << 5) + (lane >> 2);
            uint32_t af[4][4], bf[4][2];
#pragma unroll
            for (int mi = 0; mi < 4; mi++) {
                af[mi][0] = cvt_tf32(As[buf][mrow + mi*16    ][kb    ]);
                af[mi][1] = cvt_tf32(As[buf][mrow + mi*16 + 8][kb    ]);
                af[mi][2] = cvt_tf32(As[buf][mrow + mi*16    ][kb + 4]);
                af[mi][3] = cvt_tf32(As[buf][mrow + mi*16 + 8][kb + 4]);
            }
#pragma unroll
            for (int ni = 0; ni < 4; ni++) {
                bf[ni][0] = cvt_tf32(Bs[buf][kb    ][ncol + ni*8]);
                bf[ni][1] = cvt_tf32(Bs[buf][kb + 4][ncol + ni*8]);
            }
#pragma unroll
            for (int mi = 0; mi < 4; mi++)
#pragma unroll
                for (int ni = 0; ni < 4; ni++)
                    asm volatile(
                        "mma.sync.aligned.m16n8k8.row.col.f32.tf32.tf32.f32 "
                        "{%0,%1,%2,%3}, {%4,%5,%6,%7}, {%8,%9}, {%0,%1,%2,%3};\n"
                        : "+f"(acc[mi][ni][0]), "+f"(acc[mi][ni][1]),
                          "+f"(acc[mi][ni][2]), "+f"(acc[mi][ni][3])
                        : "r"(af[mi][0]), "r"(af[mi][1]), "r"(af[mi][2]), "r"(af[mi][3]),
                          "r"(bf[ni][0]), "r"(bf[ni][1]));
        }
    };

    load_chunk(0, 0);
    asm volatile("cp.async.wait_group 0;\n");
    __syncthreads();

    const int nK = Kd >> 4;
    for (int kc = 0; kc < nK; kc++) {
        int buf = kc & 1;
        if (kc + 1 < nK) load_chunk((kc + 1) << 4, buf ^ 1);
        else asm volatile("cp.async.commit_group;\n");
        compute(buf);
        asm volatile("cp.async.wait_group 0;\n");
        __syncthreads();
    }

#pragma unroll
    for (int mi = 0; mi < 4; mi++) {
        int m = m0 + (wm << 6) + mi*16 + (lane >> 2);
#pragma unroll
        for (int ni = 0; ni < 4; ni++) {
            int n = n0 + (wn << 5) + ni*8 + ((lane & 3) << 1);
            if (n < N) {
                if (epi == 4) {
                    __half* Ch = (__half*)C;
                    *(__half2*)(Ch + (size_t)m * N + n) =
                        __floats2half2_rn(tanhf(acc[mi][ni][0]), tanhf(acc[mi][ni][1]));
                    *(__half2*)(Ch + (size_t)(m + 8) * N + n) =
                        __floats2half2_rn(tanhf(acc[mi][ni][2]), tanhf(acc[mi][ni][3]));
                } else {
                    float2 v0, v1;
                    v0.x = apply_epi(acc[mi][ni][0], epi, bias, n);
                    v0.y = apply_epi(acc[mi][ni][1], epi, bias, n + 1);
                    v1.x = apply_epi(acc[mi][ni][2], epi, bias, n);
                    v1.y = apply_epi(acc[mi][ni][3], epi, bias, n + 1);
                    *(float2*)(C + (size_t)m * N + n) = v0;
                    *(float2*)(C + (size_t)(m + 8) * N + n) = v1;
                }
            }
        }
    }
}

template<int EPI>
__global__ __launch_bounds__(256) void gemm_tf32(
    const float* __restrict__ A, const float* __restrict__ B,
    float* __restrict__ C, int M, int N, int Kd, const float* __restrict__ bias)
{
    __shared__ float As[2][128][20];
    __shared__ float Bs[2][16][136];
    int n0 = blockIdx.x << 7;
    if (n0 >= N) return;
    gemm_body(A, B, C, N, Kd, bias, EPI, blockIdx.y << 7, n0, As, Bs);
}

// ---------------- WKV pass 1: per-chunk intra work + summaries --------------
#define PAD 4
__global__ __launch_bounds__(256) void wkv_chunk(
    const float* __restrict__ r, const float* __restrict__ k,
    const float* __restrict__ v, const float* __restrict__ w,
    const float* __restrict__ u,
    float* __restrict__ rw, float* __restrict__ att,
    float* __restrict__ wkvc, float* __restrict__ expws)
{
    __shared__ float sr [SCH][KK + PAD];
    __shared__ float sk [SCH][KK + PAD];
    __shared__ float sv [SCH][KK + PAD];
    __shared__ float swl[SCH][KK + PAD];
    __shared__ float swc[SCH][KK + PAD];
    __shared__ float soff[KK];
    __shared__ float sdiag[SCH];
    float* sA = &swc[0][0];

    int tid = threadIdx.x;
    int bid = blockIdx.x;
    int n = bid & (NCH - 1);
    int h = (bid / NCH) & (HH - 1);
    int b = bid / (NCH * HH);
    size_t base = ((size_t)(b * TT + n * SCH)) * DD + h * KK;

    for (int e = tid; e < SCH * KK; e += 256) {
        int t = e >> 6, c = e & 63;
        size_t gi = base + (size_t)t * DD + c;
        sr [t][c] = r[gi];
        sk [t][c] = k[gi];
        sv [t][c] = v[gi];
        swl[t][c] = fmaxf(w[gi], LOGMIN);
    }
    __syncthreads();
    if (tid < KK) {
        float c = 0.f;
        for (int t = 0; t < SCH; t++) { c += swl[t][tid]; swc[t][tid] = c; }
        expws[(size_t)bid * KK + tid] = expf(c);
        soff[tid] = swc[16][tid] - swl[16][tid];
    }
    __syncthreads();
    if (tid < SCH) {
        float acc = 0.f;
        const float4* rp = (const float4*)&sr[tid][0];
        const float4* kp = (const float4*)&sk[tid][0];
        const float4* up = (const float4*)(u + h * KK);
        for (int c = 0; c < 16; c++) {
            float4 a = rp[c], bb = kp[c], uu = up[c];
            acc += a.x*uu.x*bb.x + a.y*uu.y*bb.y + a.z*uu.z*bb.z + a.w*uu.w*bb.w;
        }
        sdiag[tid] = acc;
    }
    __syncthreads();
    for (int e = tid; e < SCH * KK; e += 256) {
        int t = e >> 6, c = e & 63;
        float wl = swl[t][c], wc = swc[t][c];
        float shft = wc - wl;
        float off  = soff[c];
        float ws   = swc[SCH - 1][c];
        float rv = sr[t][c], kv = sk[t][c];
        rw[base + (size_t)t * DD + c] = rv * expf(shft);
        sr [t][c] = rv * expf(shft - off);
        sk [t][c] = kv * expf(off - wc);
        swl[t][c] = kv * expf(ws - wc);
    }
    __syncthreads();
    for (int e = tid; e < SCH * SCH; e += 256) {
        int i = e >> 5, j = e & 31;
        float acc = 0.f;
        if (i > j) {
            const float4* rp = (const float4*)&sr[i][0];
            const float4* kp = (const float4*)&sk[j][0];
#pragma unroll 4
            for (int c = 0; c < 16; c++) {
                float4 a = rp[c], bb = kp[c];
                acc += a.x*bb.x + a.y*bb.y + a.z*bb.z + a.w*bb.w;
            }
        } else if (i == j) acc = sdiag[i];
        sA[e] = acc;
    }
    __syncthreads();
    for (int item = tid; item < SCH * 16; item += 256) {
        int t = item >> 4, v4 = item & 15;
        float4 acc = {0.f, 0.f, 0.f, 0.f};
        const float* arow = sA + t * SCH;
        for (int j = 0; j <= t; j++) {
            float a = arow[j];
            float4 vv = *(const float4*)&sv[j][v4 << 2];
            acc.x += a * vv.x; acc.y += a * vv.y;
            acc.z += a * vv.z; acc.w += a * vv.w;
        }
        *(float4*)(att + base + (size_t)t * DD + (v4 << 2)) = acc;
    }
    {
        int c0 = (tid >> 4) << 2;
        int v0 = (tid & 15) << 2;
        float acc[4][4];
#pragma unroll
        for (int i = 0; i < 4; i++)
#pragma unroll
            for (int j = 0; j < 4; j++) acc[i][j] = 0.f;
        for (int t = 0; t < SCH; t++) {
            float4 kw = *(const float4*)&swl[t][c0];
            float4 vv = *(const float4*)&sv[t][v0];
            float ka[4] = {kw.x, kw.y, kw.z, kw.w};
            float va[4] = {vv.x, vv.y, vv.z, vv.w};
#pragma unroll
            for (int i = 0; i < 4; i++)
#pragma unroll
                for (int j = 0; j < 4; j++) acc[i][j] += ka[i] * va[j];
        }
        size_t ob = (size_t)bid * (KK * KK);
#pragma unroll
        for (int i = 0; i < 4; i++) {
            float4 o4; o4.x = acc[i][0]; o4.y = acc[i][1];
            o4.z = acc[i][2]; o4.w = acc[i][3];
            *(float4*)(wkvc + ob + (size_t)(c0 + i) * KK + v0) = o4;
        }
    }
}

// ---------------- WKV pass 2: serial scan over chunks -----------------------
__global__ __launch_bounds__(1024) void wkv_scan(
    const float* __restrict__ wkvc, const float* __restrict__ expws,
    float* __restrict__ states)
{
    int bh = blockIdx.x;
    int tid = threadIdx.x;
    int c  = tid >> 4;
    int v0 = (tid & 15) << 2;
    float s0 = 0.f, s1 = 0.f, s2 = 0.f, s3 = 0.f;
    size_t eb = (size_t)bh * NCH * KK;
    size_t sb = (size_t)bh * NCH * KK * KK + (size_t)c * KK + v0;
    for (int n = 0; n < NCH; n++) {
        float wd = expws[eb + (size_t)n * KK + c];
        size_t o = sb + (size_t)n * KK * KK;
        float4 st; st.x = s0; st.y = s1; st.z = s2; st.w = s3;
        *(float4*)(states + o) = st;
        float4 wc4 = *(const float4*)(wkvc + o);
        s0 = s0 * wd + wc4.x; s1 = s1 * wd + wc4.y;
        s2 = s2 * wd + wc4.z; s3 = s3 * wd + wc4.w;
    }
}

// ---------------- WKV pass 3: apply carried state ---------------------------
__global__ __launch_bounds__(256) void wkv_state_out(
    const float* __restrict__ rw, const float* __restrict__ states,
    float* __restrict__ att)
{
    __shared__ float sst[KK][KK];
    __shared__ float srw[SCH][KK];
    int tid = threadIdx.x, bid = blockIdx.x;
    int n = bid & (NCH - 1);
    int h = (bid / NCH) & (HH - 1);
    int b = bid / (NCH * HH);
    size_t base = ((size_t)(b * TT + n * SCH)) * DD + h * KK;
    size_t stb = (size_t)bid * (KK * KK);
    for (int e = tid; e < KK * KK / 4; e += 256)
        ((float4*)&sst[0][0])[e] = ((const float4*)(states + stb))[e];
    for (int e = tid; e < SCH * KK / 4; e += 256) {
        int t = e >> 4, c4 = e & 15;
        ((float4*)&srw[t][0])[c4] =
            *(const float4*)(rw + base + (size_t)t * DD + (c4 << 2));
    }
    __syncthreads();
    int t0 = (tid >> 4) << 1;
    int v0 = (tid & 15) << 2;
    float4 acc0 = {0.f,0.f,0.f,0.f}, acc1 = {0.f,0.f,0.f,0.f};
#pragma unroll 4
    for (int c = 0; c < KK; c++) {
        float4 sv4 = *(const float4*)&sst[c][v0];
        float r0 = srw[t0][c], r1 = srw[t0 + 1][c];
        acc0.x += r0 * sv4.x; acc0.y += r0 * sv4.y;
        acc0.z += r0 * sv4.z; acc0.w += r0 * sv4.w;
        acc1.x += r1 * sv4.x; acc1.y += r1 * sv4.y;
        acc1.z += r1 * sv4.z; acc1.w += r1 * sv4.w;
    }
    float4* o0 = (float4*)(att + base + (size_t)t0 * DD + v0);
    float4* o1 = (float4*)(att + base + (size_t)(t0 + 1) * DD + v0);
    float4 p0 = *o0, p1 = *o1;
    p0.x += acc0.x; p0.y += acc0.y; p0.z += acc0.z; p0.w += acc0.w;
    p1.x += acc1.x; p1.y += acc1.y; p1.z += acc1.z; p1.w += acc1.w;
    *o0 = p0; *o1 = p1;
}

// ---------------- group-norm (per head) + gate -> fp16 ----------------------
__global__ __launch_bounds__(256) void gnorm_gate(
    const float* __restrict__ att, const float* __restrict__ gate,
    const float* __restrict__ lnw, const float* __restrict__ lnb,
    __half* __restrict__ y)
{
    int token = blockIdx.x, tid = threadIdx.x;
    size_t base = (size_t)token * DD + tid * 4;
    float4 v4 = *(const float4*)(att + base);
    float s  = v4.x + v4.y + v4.z + v4.w;
    float ss = v4.x * v4.x + v4.y * v4.y + v4.z * v4.z + v4.w * v4.w;
#pragma unroll
    for (int o = 1; o < 16; o <<= 1) {
        s  += __shfl_xor_sync(0xffffffffu, s,  o);
        ss += __shfl_xor_sync(0xffffffffu, ss, o);
    }
    float mean = s * (1.f / KK);
    float var  = ss * (1.f / KK) - mean * mean;
    float rstd = rsqrtf(var + LN_EPS);
    float4 g4 = *(const float4*)(gate + base);
    float4 w4 = *(const float4*)(lnw + tid * 4);
    float4 b4 = *(const float4*)(lnb + tid * 4);
    __half2 h0 = __floats2half2_rn(((v4.x - mean) * rstd * w4.x + b4.x) * g4.x,
                                   ((v4.y - mean) * rstd * w4.y + b4.y) * g4.y);
    __half2 h1 = __floats2half2_rn(((v4.z - mean) * rstd * w4.z + b4.z) * g4.z,
                                   ((v4.w - mean) * rstd * w4.w + b4.w) * g4.w);
    *(__half2*)(y + base)     = h0;
    *(__half2*)(y + base + 2) = h1;
}

// ---------------- launch ----------------------------------------------------
extern "C" void kernel_launch(void* const* d_in, const int* in_sizes, int n_in,
                              void* d_out, int out_size)
{
    const float* x     = (const float*)d_in[0];
    const float* tmx   = (const float*)d_in[1];
    const float* tmw   = (const float*)d_in[2];
    const float* tmk   = (const float*)d_in[3];
    const float* tmv   = (const float*)d_in[4];
    const float* tmr   = (const float*)d_in[5];
    const float* tmg   = (const float*)d_in[6];
    const float* w1    = (const float*)d_in[7];
    const float* w2    = (const float*)d_in[8];
    const float* tdec  = (const float*)d_in[9];
    const float* dw1   = (const float*)d_in[10];
    const float* dw2   = (const float*)d_in[11];
    const float* faaaa = (const float*)d_in[12];
    const float* Wr    = (const float*)d_in[13];
    const float* Wk    = (const float*)d_in[14];
    const float* Wv    = (const float*)d_in[15];
    const float* Wg    = (const float*)d_in[16];
    const float* Wo    = (const float*)d_in[17];
    const float* lnw   = (const float*)d_in[18];
    const float* lnb   = (const float*)d_in[19];
    float* out = (float*)d_out;

    float *p_xmix, *p_xw, *p_r, *p_k, *p_v, *p_gate, *p_w, *p_t1;
    float *p_rw, *p_att, *p_wkvc, *p_states, *p_expws;
    __half *p_xxxh, *p_xrh, *p_xkh, *p_xvh, *p_xgh, *p_ynh;
    __half *p_WrH, *p_WkH, *p_WvH, *p_WgH, *p_WoH, *p_W2H;
    cudaGetSymbolAddress((void**)&p_xmix,  g_xmix);
    cudaGetSymbolAddress((void**)&p_xw,    g_xw);
    cudaGetSymbolAddress((void**)&p_r,     g_r);
    cudaGetSymbolAddress((void**)&p_k,     g_k);
    cudaGetSymbolAddress((void**)&p_v,     g_v);
    cudaGetSymbolAddress((void**)&p_gate,  g_gate);
    cudaGetSymbolAddress((void**)&p_w,     g_w);
    cudaGetSymbolAddress((void**)&p_t1,    g_t1);
    cudaGetSymbolAddress((void**)&p_rw,    g_rw);
    cudaGetSymbolAddress((void**)&p_att,   g_att);
    cudaGetSymbolAddress((void**)&p_wkvc,  g_wkvc);
    cudaGetSymbolAddress((void**)&p_states,g_states);
    cudaGetSymbolAddress((void**)&p_expws, g_expws);
    cudaGetSymbolAddress((void**)&p_xxxh,  g_xxxh);
    cudaGetSymbolAddress((void**)&p_xrh,   g_xrh);
    cudaGetSymbolAddress((void**)&p_xkh,   g_xkh);
    cudaGetSymbolAddress((void**)&p_xvh,   g_xvh);
    cudaGetSymbolAddress((void**)&p_xgh,   g_xgh);
    cudaGetSymbolAddress((void**)&p_ynh,   g_ynh);
    cudaGetSymbolAddress((void**)&p_WrH,   g_WrH);
    cudaGetSymbolAddress((void**)&p_WkH,   g_WkH);
    cudaGetSymbolAddress((void**)&p_WvH,   g_WvH);
    cudaGetSymbolAddress((void**)&p_WgH,   g_WgH);
    cudaGetSymbolAddress((void**)&p_WoH,   g_WoH);
    cudaGetSymbolAddress((void**)&p_W2H,   g_W2H);

    // 0. repack weights -> fp16
    RepHArgs rp;
    rp.src[0] = Wr; rp.dst[0] = p_WrH;
    rp.src[1] = Wk; rp.dst[1] = p_WkH;
    rp.src[2] = Wv; rp.dst[2] = p_WvH;
    rp.src[3] = Wg; rp.dst[3] = p_WgH;
    rp.src[4] = Wo; rp.dst[4] = p_WoH;
    repack_wh<<<dim3(32, 32, 5), 256>>>(rp);
    repack_w2<<<(5 * DD * 32 + 255) / 256, 256>>>(w2, p_W2H);
    // 1. token shift + mix input
    prep_kernel<<<(BT * DD) / 256, 256>>>(x, tmx, p_xmix);
    // 2. xxx = tanh(xmix @ W1) -> fp16   (tf32 path, N=160, epi=4)
    gemm_tf32<4><<<dim3(2, 64), 256>>>(p_xmix, w1, (float*)p_xxxh, BT, 160, DD, nullptr);
    // 3. fused LoRA-mix GEMM: all five branch inputs
    lora_mix_gemm<<<dim3(8, 64, 5), 256>>>(p_xxxh, p_W2H, x,
                                           tmw, tmk, tmv, tmr, tmg,
                                           p_xw, p_xkh, p_xvh, p_xrh, p_xgh);
    // 4. fp16 tensor-core batch: r/k/v projections + gate (silu)
    HArgs ha;
    ha.A[0] = p_xrh; ha.Bt[0] = p_WrH; ha.C[0] = p_r;    ha.epi[0] = 0;
    ha.A[1] = p_xkh; ha.Bt[1] = p_WkH; ha.C[1] = p_k;    ha.epi[1] = 0;
    ha.A[2] = p_xvh; ha.Bt[2] = p_WvH; ha.C[2] = p_v;    ha.epi[2] = 0;
    ha.A[3] = p_xgh; ha.Bt[3] = p_WgH; ha.C[3] = p_gate; ha.epi[3] = 2;
    hgemm_batch<<<dim3(8, 64, 4), 256>>>(ha);
    // 5. decay LoRA (tf32 path): t1 = tanh(xw @ dw1); w = -exp(tdec + t1 @ dw2)
    gemm_tf32<1><<<dim3(1, 64), 256>>>(p_xw, dw1, p_t1, BT, 64, DD, nullptr);
    gemm_tf32<3><<<dim3(8, 64), 256>>>(p_t1, dw2, p_w, BT, DD, 64, tdec);
    // 6. WKV
    wkv_chunk<<<NBH * NCH, 256>>>(p_r, p_k, p_v, p_w, faaaa,
                                  p_rw, p_att, p_wkvc, p_expws);
    wkv_scan<<<NBH, 1024>>>(p_wkvc, p_expws, p_states);
    wkv_state_out<<<NBH * NCH, 256>>>(p_rw, p_states, p_att);
    // 7. group-norm + gate (fp16), then fp16 output projection
    gnorm_gate<<<BT, 256>>>(p_att, p_gate, lnw, lnb, p_ynh);
    hgemm<<<dim3(8, 64), 256>>>(p_ynh, p_WoH, out, 0);
}

// round 17
// speedup vs baseline: 1.6143x; 1.1322x over previous
#include <cuda_runtime.h>
#include <cuda_fp16.h>
#include <cuda_bf16.h>
#include <cstdint>
#include <math.h>

#define BB 4
#define TT 2048
#define DD 1024
#define HH 16
#define KK 64
#define BT (BB*TT)          /* 8192 tokens */
#define SCH 32              /* chunk length (numerically safe in fp32) */
#define NCH (TT/SCH)        /* 64 chunks per sequence */
#define NBH (BB*HH)         /* 64 (batch,head) pairs */
#define LOGMIN (-5.2983174f) /* log(0.005) */
#define LN_EPS 6.4e-4f       /* 1e-5 * 8^2 */

// ---------------- scratch (static device arrays; no runtime allocation) ----
static __device__ float g_r    [BT*DD];
static __device__ float g_k    [BT*DD];
static __device__ float g_v    [BT*DD];
static __device__ float g_gate [BT*DD];
static __device__ float g_w    [BT*DD];
static __device__ float g_rw   [BT*DD];
static __device__ float g_att  [BT*DD];
static __device__ float g_wkvc [NBH*NCH*KK*KK];
static __device__ float g_states[NBH*NCH*KK*KK];
static __device__ float g_expws[NBH*NCH*KK];
// fp16 operands
static __device__ __half g_xmixh[BT*DD];
static __device__ __half g_xxxh[BT*160];
static __device__ __half g_xwh [BT*DD];
static __device__ __half g_xrh [BT*DD];
static __device__ __half g_xkh [BT*DD];
static __device__ __half g_xvh [BT*DD];
static __device__ __half g_xgh [BT*DD];
static __device__ __half g_t1h [BT*64];
static __device__ __half g_ynh [BT*DD];
static __device__ __half g_WrH [DD*DD];   // all weights transposed [N,K] fp16
static __device__ __half g_WkH [DD*DD];
static __device__ __half g_WvH [DD*DD];
static __device__ __half g_WgH [DD*DD];
static __device__ __half g_WoH [DD*DD];
static __device__ __half g_W1H [160*DD];
static __device__ __half g_Dw1H[64*DD];
static __device__ __half g_Dw2H[DD*64];
static __device__ __half g_W2H [5*DD*32]; // [f][d][i]  (K-major per branch)

// ---------------- kernel 0: transpose + fp16-round  src[R,C] -> dst[C,R] ----
__global__ __launch_bounds__(256) void repack_t(
    const float* __restrict__ src, __half* __restrict__ dst, int R, int C)
{
    __shared__ float tile[32][33];
    int c0 = blockIdx.x * 32, r0 = blockIdx.y * 32;
    int tx = threadIdx.x & 31, ty = threadIdx.x >> 5;
#pragma unroll
    for (int i = 0; i < 32; i += 8)
        tile[ty + i][tx] = src[(size_t)(r0 + ty + i) * C + c0 + tx];
    __syncthreads();
#pragma unroll
    for (int i = 0; i < 32; i += 8)
        dst[(size_t)(c0 + ty + i) * R + r0 + tx] = __float2half_rn(tile[tx][ty + i]);
}

// ---------------- kernel 0b: repack w2 [5,32,1024] -> fp16 [5,1024,32] ------
__global__ __launch_bounds__(256) void repack_w2(const float* __restrict__ w2,
                                                 __half* __restrict__ W2H)
{
    int o = blockIdx.x * 256 + threadIdx.x;   // total 5*1024*32 = 163840
    if (o < 5 * DD * 32) {
        int i = o & 31;
        int d = (o >> 5) & (DD - 1);
        int f = o >> 15;
        W2H[o] = __float2half_rn(w2[(size_t)(f * 32 + i) * DD + d]);
    }
}

// ---------------- kernel 1: token shift + mix input (fp16 out) --------------
__global__ void prep_kernel(const float* __restrict__ x, const float* __restrict__ tmx,
                            __half* __restrict__ xmixh)
{
    size_t idx = (size_t)blockIdx.x * 256 + threadIdx.x;
    int d = (int)(idx & (DD - 1));
    int t = (int)((idx >> 10) & (TT - 1));   // DD = 2^10
    float xv = x[idx];
    float prev = (t == 0) ? 0.f : x[idx - DD];
    float xxv = prev - xv;
    xmixh[idx] = __float2half_rn(xv + xxv * tmx[d]);
}

// ---------------- cp.async helper -------------------------------------------
__device__ __forceinline__ void cp16(void* smem_dst, const void* gmem_src, bool pred) {
    uint32_t saddr = (uint32_t)__cvta_generic_to_shared(smem_dst);
    if (pred)
        asm volatile("cp.async.cg.shared.global [%0], [%1], 16;\n"
                     :: "r"(saddr), "l"(gmem_src));
    else
        asm volatile("cp.async.cg.shared.global [%0], [%1], 16, 0;\n"
                     :: "r"(saddr), "l"(gmem_src));
}

// ================= generalized fp16 tensor-core GEMM ========================
// C[M,Cs] = A[M,Kd]fp16 @ Bt[N,Kd]fp16^T (K-major B).  128x128 CTA tile,
// BK=32, 8 warps (2x4), warp 64x32, mma.m16n8k16 fp32 accum.
// epi: 0 none(float), 2 silu(float), 3 -exp(bias[n]+v)(float), 5 tanh->fp16
__device__ __forceinline__ void hgemm_body(
    const __half* __restrict__ A, const __half* __restrict__ Bt,
    void* __restrict__ Cv, const float* __restrict__ bias,
    int Kd, int N, int Cs, int epi, int m0, int n0,
    __half (*As)[128][40], __half (*Bs)[128][40])
{
    const int tid  = threadIdx.x;
    const int lane = tid & 31;
    const int wid  = tid >> 5;
    const int wm   = wid >> 2;
    const int wn   = wid & 3;

    float acc[4][4][4];
#pragma unroll
    for (int i = 0; i < 4; i++)
#pragma unroll
        for (int j = 0; j < 4; j++)
#pragma unroll
            for (int r = 0; r < 4; r++) acc[i][j][r] = 0.f;

    auto load_stage = [&](int chunk, int buf) {
        const __half* Ar = A + (size_t)m0 * Kd + chunk * 32;
        const __half* Br = Bt + (size_t)n0 * Kd + chunk * 32;
#pragma unroll
        for (int e = tid; e < 512; e += 256) {
            int row = e >> 2, c = e & 3;
            cp16(&As[buf][row][c * 8], Ar + (size_t)row * Kd + c * 8, true);
        }
#pragma unroll
        for (int e = tid; e < 512; e += 256) {
            int row = e >> 2, c = e & 3;
            cp16(&Bs[buf][row][c * 8], Br + (size_t)row * Kd + c * 8,
                 (n0 + row) < N);
        }
        asm volatile("cp.async.commit_group;\n");
    };

    const int nCh = Kd >> 5;
    load_stage(0, 0);
    asm volatile("cp.async.wait_group 0;\n");
    __syncthreads();

    for (int chunk = 0; chunk < nCh; chunk++) {
        int buf = chunk & 1;
        if (chunk + 1 < nCh) load_stage(chunk + 1, buf ^ 1);
        else asm volatile("cp.async.commit_group;\n");
#pragma unroll
        for (int ks = 0; ks < 2; ks++) {
            const int kb   = (ks << 4) + ((lane & 3) << 1);
            const int mrow = (wm << 6) + (lane >> 2);
            const int ncol = (wn << 5) + (lane >> 2);
            uint32_t af[4][4], bf[4][2];
#pragma unroll
            for (int mi = 0; mi < 4; mi++) {
                af[mi][0] = *(const uint32_t*)&As[buf][mrow + mi*16    ][kb    ];
                af[mi][1] = *(const uint32_t*)&As[buf][mrow + mi*16 + 8][kb    ];
                af[mi][2] = *(const uint32_t*)&As[buf][mrow + mi*16    ][kb + 8];
                af[mi][3] = *(const uint32_t*)&As[buf][mrow + mi*16 + 8][kb + 8];
            }
#pragma unroll
            for (int ni = 0; ni < 4; ni++) {
                bf[ni][0] = *(const uint32_t*)&Bs[buf][ncol + ni*8][kb    ];
                bf[ni][1] = *(const uint32_t*)&Bs[buf][ncol + ni*8][kb + 8];
            }
#pragma unroll
            for (int mi = 0; mi < 4; mi++)
#pragma unroll
                for (int ni = 0; ni < 4; ni++)
                    asm volatile(
                        "mma.sync.aligned.m16n8k16.row.col.f32.f16.f16.f32 "
                        "{%0,%1,%2,%3}, {%4,%5,%6,%7}, {%8,%9}, {%0,%1,%2,%3};\n"
                        : "+f"(acc[mi][ni][0]), "+f"(acc[mi][ni][1]),
                          "+f"(acc[mi][ni][2]), "+f"(acc[mi][ni][3])
                        : "r"(af[mi][0]), "r"(af[mi][1]), "r"(af[mi][2]), "r"(af[mi][3]),
                          "r"(bf[ni][0]), "r"(bf[ni][1]));
        }
        asm volatile("cp.async.wait_group 0;\n");
        __syncthreads();
    }

#pragma unroll
    for (int mi = 0; mi < 4; mi++) {
        int m = m0 + (wm << 6) + mi*16 + (lane >> 2);
#pragma unroll
        for (int ni = 0; ni < 4; ni++) {
            int n = n0 + (wn << 5) + ni*8 + ((lane & 3) << 1);
            if (n >= N) continue;
            if (epi == 5) {
                __half* Ch = (__half*)Cv;
                *(__half2*)(Ch + (size_t)m * Cs + n) =
                    __floats2half2_rn(tanhf(acc[mi][ni][0]), tanhf(acc[mi][ni][1]));
                *(__half2*)(Ch + (size_t)(m + 8) * Cs + n) =
                    __floats2half2_rn(tanhf(acc[mi][ni][2]), tanhf(acc[mi][ni][3]));
            } else {
                float* C = (float*)Cv;
                float v[4] = {acc[mi][ni][0], acc[mi][ni][1],
                              acc[mi][ni][2], acc[mi][ni][3]};
                if (epi == 2) {
#pragma unroll
                    for (int q = 0; q < 4; q++) v[q] = v[q] / (1.f + expf(-v[q]));
                } else if (epi == 3) {
                    float b0 = bias[n], b1 = bias[n + 1];
                    v[0] = -expf(b0 + v[0]); v[1] = -expf(b1 + v[1]);
                    v[2] = -expf(b0 + v[2]); v[3] = -expf(b1 + v[3]);
                }
                float2 o0; o0.x = v[0]; o0.y = v[1];
                float2 o1; o1.x = v[2]; o1.y = v[3];
                *(float2*)(C + (size_t)m * Cs + n) = o0;
                *(float2*)(C + (size_t)(m + 8) * Cs + n) = o1;
            }
        }
    }
}

struct GEnt { const __half* A; const __half* Bt; void* C; const float* bias;
              int Kd; int N; int Cs; int epi; };
struct GArgs5 { GEnt e[5]; };

__global__ __launch_bounds__(256) void hgemm_b5(GArgs5 a)
{
    __shared__ __half As[2][128][40];
    __shared__ __half Bs[2][128][40];
    const GEnt& g = a.e[blockIdx.z];
    int n0 = blockIdx.x << 7;
    if (n0 >= g.N) return;
    hgemm_body(g.A, g.Bt, g.C, g.bias, g.Kd, g.N, g.Cs, g.epi,
               blockIdx.y << 7, n0, As, Bs);
}

__global__ __launch_bounds__(256) void hgemm_one(GEnt g)
{
    __shared__ __half As[2][128][40];
    __shared__ __half Bs[2][128][40];
    int n0 = blockIdx.x << 7;
    if (n0 >= g.N) return;
    hgemm_body(g.A, g.Bt, g.C, g.bias, g.Kd, g.N, g.Cs, g.epi,
               blockIdx.y << 7, n0, As, Bs);
}

// ================= fused LoRA-mix GEMM (fp16, K=32) =========================
__global__ __launch_bounds__(256) void lora_mix_gemm(
    const __half* __restrict__ xxxh,   // [BT,160]
    const __half* __restrict__ W2H,    // [5][1024][32]
    const float* __restrict__ x,
    const float* __restrict__ tmw, const float* __restrict__ tmk,
    const float* __restrict__ tmv, const float* __restrict__ tmr,
    const float* __restrict__ tmg,
    __half* __restrict__ xwh,
    __half* __restrict__ xkh, __half* __restrict__ xvh,
    __half* __restrict__ xrh, __half* __restrict__ xgh)
{
    __shared__ __half As[128][40];
    __shared__ __half Bs[128][40];
    const int tid  = threadIdx.x;
    const int lane = tid & 31;
    const int wid  = tid >> 5;
    const int wm   = wid >> 2;
    const int wn   = wid & 3;
    const int f  = blockIdx.z;
    const int m0 = blockIdx.y << 7;
    const int n0 = blockIdx.x << 7;

    {
        const __half* Ar = xxxh + (size_t)m0 * 160 + f * 32;
        const __half* Br = W2H + (size_t)f * DD * 32 + (size_t)n0 * 32;
#pragma unroll
        for (int e = tid; e < 512; e += 256) {
            int row = e >> 2, c = e & 3;
            cp16(&As[row][c * 8], Ar + (size_t)row * 160 + c * 8, true);
        }
#pragma unroll
        for (int e = tid; e < 512; e += 256) {
            int row = e >> 2, c = e & 3;
            cp16(&Bs[row][c * 8], Br + (size_t)row * 32 + c * 8, true);
        }
        asm volatile("cp.async.commit_group;\n");
        asm volatile("cp.async.wait_group 0;\n");
        __syncthreads();
    }

    float acc[4][4][4];
#pragma unroll
    for (int i = 0; i < 4; i++)
#pragma unroll
        for (int j = 0; j < 4; j++)
#pragma unroll
            for (int r = 0; r < 4; r++) acc[i][j][r] = 0.f;

#pragma unroll
    for (int ks = 0; ks < 2; ks++) {
        const int kb   = (ks << 4) + ((lane & 3) << 1);
        const int mrow = (wm << 6) + (lane >> 2);
        const int ncol = (wn << 5) + (lane >> 2);
        uint32_t af[4][4], bf[4][2];
#pragma unroll
        for (int mi = 0; mi < 4; mi++) {
            af[mi][0] = *(const uint32_t*)&As[mrow + mi*16    ][kb    ];
            af[mi][1] = *(const uint32_t*)&As[mrow + mi*16 + 8][kb    ];
            af[mi][2] = *(const uint32_t*)&As[mrow + mi*16    ][kb + 8];
            af[mi][3] = *(const uint32_t*)&As[mrow + mi*16 + 8][kb + 8];
        }
#pragma unroll
        for (int ni = 0; ni < 4; ni++) {
            bf[ni][0] = *(const uint32_t*)&Bs[ncol + ni*8][kb    ];
            bf[ni][1] = *(const uint32_t*)&Bs[ncol + ni*8][kb + 8];
        }
#pragma unroll
        for (int mi = 0; mi < 4; mi++)
#pragma unroll
            for (int ni = 0; ni < 4; ni++)
                asm volatile(
                    "mma.sync.aligned.m16n8k16.row.col.f32.f16.f16.f32 "
                    "{%0,%1,%2,%3}, {%4,%5,%6,%7}, {%8,%9}, {%0,%1,%2,%3};\n"
                    : "+f"(acc[mi][ni][0]), "+f"(acc[mi][ni][1]),
                      "+f"(acc[mi][ni][2]), "+f"(acc[mi][ni][3])
                    : "r"(af[mi][0]), "r"(af[mi][1]), "r"(af[mi][2]), "r"(af[mi][3]),
                      "r"(bf[ni][0]), "r"(bf[ni][1]));
    }

    const float* tmsel = (f == 0) ? tmw : (f == 1) ? tmk :
                         (f == 2) ? tmv : (f == 3) ? tmr : tmg;
    __half* osel = (f == 0) ? xwh : (f == 1) ? xkh : (f == 2) ? xvh :
                   (f == 3) ? xrh : xgh;

#pragma unroll
    for (int mi = 0; mi < 4; mi++) {
        int m = m0 + (wm << 6) + mi*16 + (lane >> 2);
#pragma unroll
        for (int ni = 0; ni < 4; ni++) {
            int n = n0 + (wn << 5) + ni*8 + ((lane & 3) << 1);
            float2 tm2 = *(const float2*)(tmsel + n);
#pragma unroll
            for (int rr = 0; rr < 2; rr++) {
                int mm = m + rr * 8;
                size_t gi = (size_t)mm * DD + n;
                float2 xv2 = *(const float2*)(x + gi);
                float2 xp2;
                if ((mm & (TT - 1)) == 0) { xp2.x = 0.f; xp2.y = 0.f; }
                else xp2 = *(const float2*)(x + gi - DD);
                float v0 = xv2.x + (xp2.x - xv2.x) * (tm2.x + acc[mi][ni][rr*2+0]);
                float v1 = xv2.y + (xp2.y - xv2.y) * (tm2.y + acc[mi][ni][rr*2+1]);
                *(__half2*)(osel + gi) = __floats2half2_rn(v0, v1);
            }
        }
    }
}

// ---------------- WKV pass 1: per-chunk intra work + summaries --------------
#define PAD 4
__global__ __launch_bounds__(256) void wkv_chunk(
    const float* __restrict__ r, const float* __restrict__ k,
    const float* __restrict__ v, const float* __restrict__ w,
    const float* __restrict__ u,
    float* __restrict__ rw, float* __restrict__ att,
    float* __restrict__ wkvc, float* __restrict__ expws)
{
    __shared__ float sr [SCH][KK + PAD];
    __shared__ float sk [SCH][KK + PAD];
    __shared__ float sv [SCH][KK + PAD];
    __shared__ float swl[SCH][KK + PAD];
    __shared__ float swc[SCH][KK + PAD];
    __shared__ float soff[KK];
    __shared__ float sdiag[SCH];
    float* sA = &swc[0][0];

    int tid = threadIdx.x;
    int bid = blockIdx.x;
    int n = bid & (NCH - 1);
    int h = (bid / NCH) & (HH - 1);
    int b = bid / (NCH * HH);
    size_t base = ((size_t)(b * TT + n * SCH)) * DD + h * KK;

    for (int e = tid; e < SCH * KK; e += 256) {
        int t = e >> 6, c = e & 63;
        size_t gi = base + (size_t)t * DD + c;
        sr [t][c] = r[gi];
        sk [t][c] = k[gi];
        sv [t][c] = v[gi];
        swl[t][c] = fmaxf(w[gi], LOGMIN);
    }
    __syncthreads();
    if (tid < KK) {
        float c = 0.f;
        for (int t = 0; t < SCH; t++) { c += swl[t][tid]; swc[t][tid] = c; }
        expws[(size_t)bid * KK + tid] = expf(c);
        soff[tid] = swc[16][tid] - swl[16][tid];
    }
    __syncthreads();
    if (tid < SCH) {
        float acc = 0.f;
        const float4* rp = (const float4*)&sr[tid][0];
        const float4* kp = (const float4*)&sk[tid][0];
        const float4* up = (const float4*)(u + h * KK);
        for (int c = 0; c < 16; c++) {
            float4 a = rp[c], bb = kp[c], uu = up[c];
            acc += a.x*uu.x*bb.x + a.y*uu.y*bb.y + a.z*uu.z*bb.z + a.w*uu.w*bb.w;
        }
        sdiag[tid] = acc;
    }
    __syncthreads();
    for (int e = tid; e < SCH * KK; e += 256) {
        int t = e >> 6, c = e & 63;
        float wl = swl[t][c], wc = swc[t][c];
        float shft = wc - wl;
        float off  = soff[c];
        float ws   = swc[SCH - 1][c];
        float rv = sr[t][c], kv = sk[t][c];
        rw[base + (size_t)t * DD + c] = rv * expf(shft);
        sr [t][c] = rv * expf(shft - off);
        sk [t][c] = kv * expf(off - wc);
        swl[t][c] = kv * expf(ws - wc);
    }
    __syncthreads();
    for (int e = tid; e < SCH * SCH; e += 256) {
        int i = e >> 5, j = e & 31;
        float acc = 0.f;
        if (i > j) {
            const float4* rp = (const float4*)&sr[i][0];
            const float4* kp = (const float4*)&sk[j][0];
#pragma unroll 4
            for (int c = 0; c < 16; c++) {
                float4 a = rp[c], bb = kp[c];
                acc += a.x*bb.x + a.y*bb.y + a.z*bb.z + a.w*bb.w;
            }
        } else if (i == j) acc = sdiag[i];
        sA[e] = acc;
    }
    __syncthreads();
    for (int item = tid; item < SCH * 16; item += 256) {
        int t = item >> 4, v4 = item & 15;
        float4 acc = {0.f, 0.f, 0.f, 0.f};
        const float* arow = sA + t * SCH;
        for (int j = 0; j <= t; j++) {
            float a = arow[j];
            float4 vv = *(const float4*)&sv[j][v4 << 2];
            acc.x += a * vv.x; acc.y += a * vv.y;
            acc.z += a * vv.z; acc.w += a * vv.w;
        }
        *(float4*)(att + base + (size_t)t * DD + (v4 << 2)) = acc;
    }
    {
        int c0 = (tid >> 4) << 2;
        int v0 = (tid & 15) << 2;
        float acc[4][4];
#pragma unroll
        for (int i = 0; i < 4; i++)
#pragma unroll
            for (int j = 0; j < 4; j++) acc[i][j] = 0.f;
        for (int t = 0; t < SCH; t++) {
            float4 kw = *(const float4*)&swl[t][c0];
            float4 vv = *(const float4*)&sv[t][v0];
            float ka[4] = {kw.x, kw.y, kw.z, kw.w};
            float va[4] = {vv.x, vv.y, vv.z, vv.w};
#pragma unroll
            for (int i = 0; i < 4; i++)
#pragma unroll
                for (int j = 0; j < 4; j++) acc[i][j] += ka[i] * va[j];
        }
        size_t ob = (size_t)bid * (KK * KK);
#pragma unroll
        for (int i = 0; i < 4; i++) {
            float4 o4; o4.x = acc[i][0]; o4.y = acc[i][1];
            o4.z = acc[i][2]; o4.w = acc[i][3];
            *(float4*)(wkvc + ob + (size_t)(c0 + i) * KK + v0) = o4;
        }
    }
}

// ---------------- WKV pass 2: serial scan over chunks -----------------------
__global__ __launch_bounds__(1024) void wkv_scan(
    const float* __restrict__ wkvc, const float* __restrict__ expws,
    float* __restrict__ states)
{
    int bh = blockIdx.x;
    int tid = threadIdx.x;
    int c  = tid >> 4;
    int v0 = (tid & 15) << 2;
    float s0 = 0.f, s1 = 0.f, s2 = 0.f, s3 = 0.f;
    size_t eb = (size_t)bh * NCH * KK;
    size_t sb = (size_t)bh * NCH * KK * KK + (size_t)c * KK + v0;
    for (int n = 0; n < NCH; n++) {
        float wd = expws[eb + (size_t)n * KK + c];
        size_t o = sb + (size_t)n * KK * KK;
        float4 st; st.x = s0; st.y = s1; st.z = s2; st.w = s3;
        *(float4*)(states + o) = st;
        float4 wc4 = *(const float4*)(wkvc + o);
        s0 = s0 * wd + wc4.x; s1 = s1 * wd + wc4.y;
        s2 = s2 * wd + wc4.z; s3 = s3 * wd + wc4.w;
    }
}

// ---------------- WKV pass 3: apply carried state ---------------------------
__global__ __launch_bounds__(256) void wkv_state_out(
    const float* __restrict__ rw, const float* __restrict__ states,
    float* __restrict__ att)
{
    __shared__ float sst[KK][KK];
    __shared__ float srw[SCH][KK];
    int tid = threadIdx.x, bid = blockIdx.x;
    int n = bid & (NCH - 1);
    int h = (bid / NCH) & (HH - 1);
    int b = bid / (NCH * HH);
    size_t base = ((size_t)(b * TT + n * SCH)) * DD + h * KK;
    size_t stb = (size_t)bid * (KK * KK);
    for (int e = tid; e < KK * KK / 4; e += 256)
        ((float4*)&sst[0][0])[e] = ((const float4*)(states + stb))[e];
    for (int e = tid; e < SCH * KK / 4; e += 256) {
        int t = e >> 4, c4 = e & 15;
        ((float4*)&srw[t][0])[c4] =
            *(const float4*)(rw + base + (size_t)t * DD + (c4 << 2));
    }
    __syncthreads();
    int t0 = (tid >> 4) << 1;
    int v0 = (tid & 15) << 2;
    float4 acc0 = {0.f,0.f,0.f,0.f}, acc1 = {0.f,0.f,0.f,0.f};
#pragma unroll 4
    for (int c = 0; c < KK; c++) {
        float4 sv4 = *(const float4*)&sst[c][v0];
        float r0 = srw[t0][c], r1 = srw[t0 + 1][c];
        acc0.x += r0 * sv4.x; acc0.y += r0 * sv4.y;
        acc0.z += r0 * sv4.z; acc0.w += r0 * sv4.w;
        acc1.x += r1 * sv4.x; acc1.y += r1 * sv4.y;
        acc1.z += r1 * sv4.z; acc1.w += r1 * sv4.w;
    }
    float4* o0 = (float4*)(att + base + (size_t)t0 * DD + v0);
    float4* o1 = (float4*)(att + base + (size_t)(t0 + 1) * DD + v0);
    float4 p0 = *o0, p1 = *o1;
    p0.x += acc0.x; p0.y += acc0.y; p0.z += acc0.z; p0.w += acc0.w;
    p1.x += acc1.x; p1.y += acc1.y; p1.z += acc1.z; p1.w += acc1.w;
    *o0 = p0; *o1 = p1;
}

// ---------------- group-norm (per head) + gate -> fp16 ----------------------
__global__ __launch_bounds__(256) void gnorm_gate(
    const float* __restrict__ att, const float* __restrict__ gate,
    const float* __restrict__ lnw, const float* __restrict__ lnb,
    __half* __restrict__ y)
{
    int token = blockIdx.x, tid = threadIdx.x;
    size_t base = (size_t)token * DD + tid * 4;
    float4 v4 = *(const float4*)(att + base);
    float s  = v4.x + v4.y + v4.z + v4.w;
    float ss = v4.x * v4.x + v4.y * v4.y + v4.z * v4.z + v4.w * v4.w;
#pragma unroll
    for (int o = 1; o < 16; o <<= 1) {
        s  += __shfl_xor_sync(0xffffffffu, s,  o);
        ss += __shfl_xor_sync(0xffffffffu, ss, o);
    }
    float mean = s * (1.f / KK);
    float var  = ss * (1.f / KK) - mean * mean;
    float rstd = rsqrtf(var + LN_EPS);
    float4 g4 = *(const float4*)(gate + base);
    float4 w4 = *(const float4*)(lnw + tid * 4);
    float4 b4 = *(const float4*)(lnb + tid * 4);
    __half2 h0 = __floats2half2_rn(((v4.x - mean) * rstd * w4.x + b4.x) * g4.x,
                                   ((v4.y - mean) * rstd * w4.y + b4.y) * g4.y);
    __half2 h1 = __floats2half2_rn(((v4.z - mean) * rstd * w4.z + b4.z) * g4.z,
                                   ((v4.w - mean) * rstd * w4.w + b4.w) * g4.w);
    *(__half2*)(y + base)     = h0;
    *(__half2*)(y + base + 2) = h1;
}

// ---------------- launch ----------------------------------------------------
extern "C" void kernel_launch(void* const* d_in, const int* in_sizes, int n_in,
                              void* d_out, int out_size)
{
    const float* x     = (const float*)d_in[0];
    const float* tmx   = (const float*)d_in[1];
    const float* tmw   = (const float*)d_in[2];
    const float* tmk   = (const float*)d_in[3];
    const float* tmv   = (const float*)d_in[4];
    const float* tmr   = (const float*)d_in[5];
    const float* tmg   = (const float*)d_in[6];
    const float* w1    = (const float*)d_in[7];
    const float* w2    = (const float*)d_in[8];
    const float* tdec  = (const float*)d_in[9];
    const float* dw1   = (const float*)d_in[10];
    const float* dw2   = (const float*)d_in[11];
    const float* faaaa = (const float*)d_in[12];
    const float* Wr    = (const float*)d_in[13];
    const float* Wk    = (const float*)d_in[14];
    const float* Wv    = (const float*)d_in[15];
    const float* Wg    = (const float*)d_in[16];
    const float* Wo    = (const float*)d_in[17];
    const float* lnw   = (const float*)d_in[18];
    const float* lnb   = (const float*)d_in[19];
    float* out = (float*)d_out;

    float *p_r, *p_k, *p_v, *p_gate, *p_w, *p_rw, *p_att;
    float *p_wkvc, *p_states, *p_expws;
    __half *p_xmixh, *p_xxxh, *p_xwh, *p_xrh, *p_xkh, *p_xvh, *p_xgh, *p_t1h, *p_ynh;
    __half *p_WrH, *p_WkH, *p_WvH, *p_WgH, *p_WoH, *p_W1H, *p_Dw1H, *p_Dw2H, *p_W2H;
    cudaGetSymbolAddress((void**)&p_r,     g_r);
    cudaGetSymbolAddress((void**)&p_k,     g_k);
    cudaGetSymbolAddress((void**)&p_v,     g_v);
    cudaGetSymbolAddress((void**)&p_gate,  g_gate);
    cudaGetSymbolAddress((void**)&p_w,     g_w);
    cudaGetSymbolAddress((void**)&p_rw,    g_rw);
    cudaGetSymbolAddress((void**)&p_att,   g_att);
    cudaGetSymbolAddress((void**)&p_wkvc,  g_wkvc);
    cudaGetSymbolAddress((void**)&p_states,g_states);
    cudaGetSymbolAddress((void**)&p_expws, g_expws);
    cudaGetSymbolAddress((void**)&p_xmixh, g_xmixh);
    cudaGetSymbolAddress((void**)&p_xxxh,  g_xxxh);
    cudaGetSymbolAddress((void**)&p_xwh,   g_xwh);
    cudaGetSymbolAddress((void**)&p_xrh,   g_xrh);
    cudaGetSymbolAddress((void**)&p_xkh,   g_xkh);
    cudaGetSymbolAddress((void**)&p_xvh,   g_xvh);
    cudaGetSymbolAddress((void**)&p_xgh,   g_xgh);
    cudaGetSymbolAddress((void**)&p_t1h,   g_t1h);
    cudaGetSymbolAddress((void**)&p_ynh,   g_ynh);
    cudaGetSymbolAddress((void**)&p_WrH,   g_WrH);
    cudaGetSymbolAddress((void**)&p_WkH,   g_WkH);
    cudaGetSymbolAddress((void**)&p_WvH,   g_WvH);
    cudaGetSymbolAddress((void**)&p_WgH,   g_WgH);
    cudaGetSymbolAddress((void**)&p_WoH,   g_WoH);
    cudaGetSymbolAddress((void**)&p_W1H,   g_W1H);
    cudaGetSymbolAddress((void**)&p_Dw1H,  g_Dw1H);
    cudaGetSymbolAddress((void**)&p_Dw2H,  g_Dw2H);
    cudaGetSymbolAddress((void**)&p_W2H,   g_W2H);

    // 0. repack all weights -> fp16 (transposed [N,K])
    repack_t<<<dim3(32, 32), 256>>>(Wr,  p_WrH,  DD, DD);
    repack_t<<<dim3(32, 32), 256>>>(Wk,  p_WkH,  DD, DD);
    repack_t<<<dim3(32, 32), 256>>>(Wv,  p_WvH,  DD, DD);
    repack_t<<<dim3(32, 32), 256>>>(Wg,  p_WgH,  DD, DD);
    repack_t<<<dim3(32, 32), 256>>>(Wo,  p_WoH,  DD, DD);
    repack_t<<<dim3(5, 32),  256>>>(w1,  p_W1H,  DD, 160);
    repack_t<<<dim3(2, 32),  256>>>(dw1, p_Dw1H, DD, 64);
    repack_t<<<dim3(32, 2),  256>>>(dw2, p_Dw2H, 64, DD);
    repack_w2<<<(5 * DD * 32 + 255) / 256, 256>>>(w2, p_W2H);
    // 1. token shift + mix input (fp16)
    prep_kernel<<<(BT * DD) / 256, 256>>>(x, tmx, p_xmixh);
    // 2. xxx = tanh(xmix @ W1) -> fp16   (fp16 GEMM, N=160)
    {
        GEnt g; g.A = p_xmixh; g.Bt = p_W1H; g.C = p_xxxh; g.bias = nullptr;
        g.Kd = DD; g.N = 160; g.Cs = 160; g.epi = 5;
        hgemm_one<<<dim3(2, 64), 256>>>(g);
    }
    // 3. fused LoRA-mix GEMM: all five branch inputs (fp16)
    lora_mix_gemm<<<dim3(8, 64, 5), 256>>>(p_xxxh, p_W2H, x,
                                           tmw, tmk, tmv, tmr, tmg,
                                           p_xwh, p_xkh, p_xvh, p_xrh, p_xgh);
    // 4. batched fp16 GEMMs: r/k/v, gate (silu), decay stage 1 (tanh->fp16)
    GArgs5 ga;
    ga.e[0] = {p_xrh, p_WrH,  p_r,    nullptr, DD, DD, DD, 0};
    ga.e[1] = {p_xkh, p_WkH,  p_k,    nullptr, DD, DD, DD, 0};
    ga.e[2] = {p_xvh, p_WvH,  p_v,    nullptr, DD, DD, DD, 0};
    ga.e[3] = {p_xgh, p_WgH,  p_gate, nullptr, DD, DD, DD, 2};
    ga.e[4] = {p_xwh, p_Dw1H, p_t1h,  nullptr, DD, 64, 64, 5};
    hgemm_b5<<<dim3(8, 64, 5), 256>>>(ga);
    // 5. decay stage 2: w = -exp(tdec + t1 @ dw2)   (fp16, K=64)
    {
        GEnt g; g.A = p_t1h; g.Bt = p_Dw2H; g.C = p_w; g.bias = tdec;
        g.Kd = 64; g.N = DD; g.Cs = DD; g.epi = 3;
        hgemm_one<<<dim3(8, 64), 256>>>(g);
    }
    // 6. WKV
    wkv_chunk<<<NBH * NCH, 256>>>(p_r, p_k, p_v, p_w, faaaa,
                                  p_rw, p_att, p_wkvc, p_expws);
    wkv_scan<<<NBH, 1024>>>(p_wkvc, p_expws, p_states);
    wkv_state_out<<<NBH * NCH, 256>>>(p_rw, p_states, p_att);
    // 7. group-norm + gate (fp16), then fp16 output projection
    gnorm_gate<<<BT, 256>>>(p_att, p_gate, lnw, lnb, p_ynh);
    {
        GEnt g; g.A = p_ynh; g.Bt = p_WoH; g.C = out; g.bias = nullptr;
        g.Kd = DD; g.N = DD; g.Cs = DD; g.epi = 0;
        hgemm_one<<<dim3(8, 64), 256>>>(g);
    }
}